// round 4
// baseline (speedup 1.0000x reference)
#include <cuda_runtime.h>
#include <cuda_bf16.h>
#include <math.h>

#define NN 100000
#define NE 1600000
#define INF 128
#define HID 32
#define NPAIRS 4096
#define SCAN_BS 1024
#define NB ((NN + SCAN_BS - 1) / SCAN_BS)   // 98

// scratch (device globals)
__device__ float g_xr[NN * 160];       // per-node per-relation combined msgs [n][r][32]
__device__ float g_agg[NN * 32];       // agg init (loop term + bias)
__device__ float g_h1[NN * 32];
__device__ float g_h2[NN * 32];
__device__ float g_h3[NN * 32];
__device__ int   g_deg[NN];
__device__ int   g_bsum[NB + 1];
__device__ int   g_rowptr[NN + 1];
__device__ int   g_cursor[NN];
__device__ int2  g_meta[NE];           // {src | etype<<17, mask_bits} grouped by dst

// ---------------------------------------------------------------------------
// Split-TF32 tensor-core transform + relation-expansion epilogue.
// out96[n][j] = sum_d x[n][d]*Wall[d][j]  (j<64: basis b=j>>5,o=j&31; j>=64: loop)
// Epilogue: xr[n][r][o] = c0[r]*out[o] + c1[r]*out[32+o];  agg[n][o] = out[64+o]+bias[o]
// ---------------------------------------------------------------------------
#define XS_STRIDE 36
#define WS_STRIDE 100
#define OS_STRIDE 104
#define XS_BYTES  (128 * XS_STRIDE * 8)           // 36864
#define WS_BYTES  (32 * WS_STRIDE * 8)            // 25600
#define TSMEM     (XS_BYTES + WS_BYTES)           // 62464
#define CL_OFF    (128 * OS_STRIDE)               // float index just past outs (53248B)

__device__ __forceinline__ unsigned f2tf(float f) {
    unsigned r; asm("cvt.rna.tf32.f32 %0, %1;" : "=r"(r) : "f"(f)); return r;
}
__device__ __forceinline__ void mma8(float* c, const unsigned* a, const unsigned* b) {
    asm volatile("mma.sync.aligned.m16n8k8.row.col.f32.tf32.tf32.f32 "
                 "{%0,%1,%2,%3}, {%4,%5,%6,%7}, {%8,%9}, {%0,%1,%2,%3};"
                 : "+f"(c[0]), "+f"(c[1]), "+f"(c[2]), "+f"(c[3])
                 : "r"(a[0]), "r"(a[1]), "r"(a[2]), "r"(a[3]), "r"(b[0]), "r"(b[1]));
}

template <int DIN>
__global__ __launch_bounds__(256, 2)
void transform_mma(const float* __restrict__ xin,
                   const float* __restrict__ V,       // [2][DIN][32]
                   const float* __restrict__ loopw,   // [DIN][32]
                   const float* __restrict__ bias,    // [32]
                   const float* __restrict__ comp,    // [5][2]
                   float* __restrict__ xr,            // [NN][5][32]
                   float* __restrict__ agg,           // [NN][32]
                   int nnodes)
{
    extern __shared__ char smraw[];
    float2* xs = (float2*)smraw;                 // [128][XS_STRIDE] {hi,lo}
    float2* ws = (float2*)(smraw + XS_BYTES);    // [32][WS_STRIDE]  {hi,lo}
    float*  outs = (float*)smraw;                // reused after compute
    float*  cl   = ((float*)smraw) + CL_OFF;     // comp copy (10 floats)

    const int tid = threadIdx.x;
    const int lane = tid & 31, wid = tid >> 5;
    const int warpM = wid & 3, warpN = wid >> 2;
    const int gid = lane >> 2, tig = lane & 3;
    const int base = blockIdx.x * 128;

    float c[2][6][4];
#pragma unroll
    for (int mt = 0; mt < 2; mt++)
#pragma unroll
        for (int nt = 0; nt < 6; nt++)
#pragma unroll
            for (int q = 0; q < 4; q++) c[mt][nt][q] = 0.f;

    const int NCHUNK = DIN / 32;
#pragma unroll 1
    for (int ch = 0; ch < NCHUNK; ch++) {
        const int kbase = ch * 32;
        if (ch) __syncthreads();
        for (int idx = tid; idx < 128 * 32; idx += 256) {
            int row = idx >> 5, col = idx & 31;
            int node = base + row;
            float v = (node < nnodes) ? xin[(long)node * DIN + kbase + col] : 0.f;
            unsigned hb = f2tf(v);
            float hf = __uint_as_float(hb);
            unsigned lb = f2tf(v - hf);
            xs[row * XS_STRIDE + col] = make_float2(hf, __uint_as_float(lb));
        }
        for (int idx = tid; idx < 32 * 96; idx += 256) {
            int k = idx / 96, j = idx - k * 96;
            int d = kbase + k;
            float w = (j < 64) ? V[(j >> 5) * DIN * 32 + d * 32 + (j & 31)]
                               : loopw[d * 32 + (j - 64)];
            unsigned hb = f2tf(w);
            float hf = __uint_as_float(hb);
            unsigned lb = f2tf(w - hf);
            ws[k * WS_STRIDE + j] = make_float2(hf, __uint_as_float(lb));
        }
        __syncthreads();

#pragma unroll
        for (int ks = 0; ks < 32; ks += 8) {
            unsigned ahi[2][4], alo[2][4];
#pragma unroll
            for (int mt = 0; mt < 2; mt++) {
                int r0 = warpM * 32 + mt * 16 + gid;
                float2 a0 = xs[(r0    ) * XS_STRIDE + ks + tig];
                float2 a1 = xs[(r0 + 8) * XS_STRIDE + ks + tig];
                float2 a2 = xs[(r0    ) * XS_STRIDE + ks + tig + 4];
                float2 a3 = xs[(r0 + 8) * XS_STRIDE + ks + tig + 4];
                ahi[mt][0] = __float_as_uint(a0.x); alo[mt][0] = __float_as_uint(a0.y);
                ahi[mt][1] = __float_as_uint(a1.x); alo[mt][1] = __float_as_uint(a1.y);
                ahi[mt][2] = __float_as_uint(a2.x); alo[mt][2] = __float_as_uint(a2.y);
                ahi[mt][3] = __float_as_uint(a3.x); alo[mt][3] = __float_as_uint(a3.y);
            }
            unsigned bhi[6][2], blo[6][2];
#pragma unroll
            for (int nt = 0; nt < 6; nt++) {
                int n = warpN * 48 + nt * 8 + gid;
                float2 b0 = ws[(ks + tig    ) * WS_STRIDE + n];
                float2 b1 = ws[(ks + tig + 4) * WS_STRIDE + n];
                bhi[nt][0] = __float_as_uint(b0.x); blo[nt][0] = __float_as_uint(b0.y);
                bhi[nt][1] = __float_as_uint(b1.x); blo[nt][1] = __float_as_uint(b1.y);
            }
#pragma unroll
            for (int mt = 0; mt < 2; mt++)
#pragma unroll
                for (int nt = 0; nt < 6; nt++) {
                    mma8(c[mt][nt], ahi[mt], bhi[nt]);
                    mma8(c[mt][nt], ahi[mt], blo[nt]);
                    mma8(c[mt][nt], alo[mt], bhi[nt]);
                }
        }
    }
    __syncthreads();   // compute smem dead; reuse as outs

    if (tid < 10) cl[tid] = comp[tid];
#pragma unroll
    for (int mt = 0; mt < 2; mt++)
#pragma unroll
        for (int nt = 0; nt < 6; nt++) {
            int r0 = warpM * 32 + mt * 16 + gid;
            int c0 = warpN * 48 + nt * 8 + tig * 2;
            outs[(r0    ) * OS_STRIDE + c0    ] = c[mt][nt][0];
            outs[(r0    ) * OS_STRIDE + c0 + 1] = c[mt][nt][1];
            outs[(r0 + 8) * OS_STRIDE + c0    ] = c[mt][nt][2];
            outs[(r0 + 8) * OS_STRIDE + c0 + 1] = c[mt][nt][3];
        }
    __syncthreads();

    // xr expansion: 128 rows x 160 (= 5 rel x 32 o)
    for (int idx = tid; idx < 128 * 160; idx += 256) {
        int row = idx / 160, j = idx - row * 160;
        int node = base + row;
        if (node >= nnodes) continue;
        int r = j >> 5, o = j & 31;
        float v0 = outs[row * OS_STRIDE + o];
        float v1 = outs[row * OS_STRIDE + 32 + o];
        xr[(long)node * 160 + j] = fmaf(cl[r * 2], v0, cl[r * 2 + 1] * v1);
    }
    // agg init: loop term + bias
    for (int idx = tid; idx < 128 * 32; idx += 256) {
        int row = idx >> 5, o = idx & 31;
        int node = base + row;
        if (node >= nnodes) continue;
        agg[(long)node * 32 + o] = outs[row * OS_STRIDE + 64 + o] + bias[o];
    }
}

// ------------------------ CSR build ---------------------------------------
__global__ void k_zero(int* p, int n)
{
    int i = blockIdx.x * blockDim.x + threadIdx.x;
    if (i < n) p[i] = 0;
}
__global__ void k_hist(const int* __restrict__ dst, int* __restrict__ deg, int ne)
{
    int i = blockIdx.x * blockDim.x + threadIdx.x;
    if (i < ne) atomicAdd(&deg[dst[i]], 1);
}
__global__ void k_blocksum(const int* __restrict__ deg, int* __restrict__ bsum, int n)
{
    __shared__ int wsum[32];
    int i = blockIdx.x * SCAN_BS + threadIdx.x;
    int v = (i < n) ? deg[i] : 0;
#pragma unroll
    for (int o = 16; o; o >>= 1) v += __shfl_down_sync(0xFFFFFFFFu, v, o);
    int lane = threadIdx.x & 31, wid = threadIdx.x >> 5;
    if (lane == 0) wsum[wid] = v;
    __syncthreads();
    if (wid == 0) {
        int x = wsum[lane];
#pragma unroll
        for (int o = 16; o; o >>= 1) x += __shfl_down_sync(0xFFFFFFFFu, x, o);
        if (lane == 0) bsum[blockIdx.x] = x;
    }
}
__global__ void k_scantop(int* __restrict__ bsum, int nb, int* __restrict__ rowptr_end)
{
    __shared__ int s[128];
    int t = threadIdx.x;
    int v = (t < nb) ? bsum[t] : 0;
    s[t] = v;
    __syncthreads();
#pragma unroll
    for (int o = 1; o < 128; o <<= 1) {
        int y = (t >= o) ? s[t - o] : 0;
        __syncthreads();
        s[t] += y;
        __syncthreads();
    }
    if (t < nb) bsum[t] = s[t] - v;
    if (t == 127) *rowptr_end = s[127];
}
__global__ void k_scanapply(const int* __restrict__ deg, const int* __restrict__ bsum,
                            int* __restrict__ rowptr, int* __restrict__ cursor, int n)
{
    __shared__ int wsum[32];
    int i = blockIdx.x * SCAN_BS + threadIdx.x;
    int v = (i < n) ? deg[i] : 0;
    int lane = threadIdx.x & 31, wid = threadIdx.x >> 5;
    unsigned fm = 0xFFFFFFFFu;
    int x = v;
#pragma unroll
    for (int o = 1; o < 32; o <<= 1) {
        int y = __shfl_up_sync(fm, x, o);
        if (lane >= o) x += y;
    }
    if (lane == 31) wsum[wid] = x;
    __syncthreads();
    if (wid == 0) {
        int w = wsum[lane];
        int wx = w;
#pragma unroll
        for (int o = 1; o < 32; o <<= 1) {
            int y = __shfl_up_sync(fm, wx, o);
            if (lane >= o) wx += y;
        }
        wsum[lane] = wx - w;
    }
    __syncthreads();
    int excl = (x - v) + wsum[wid] + bsum[blockIdx.x];
    if (i < n) { rowptr[i] = excl; cursor[i] = excl; }
}
__global__ void k_scatter(const int* __restrict__ src, const int* __restrict__ dst,
                          const int* __restrict__ etype, const float* __restrict__ mask,
                          int* __restrict__ cursor, int2* __restrict__ meta, int ne)
{
    int e = blockIdx.x * blockDim.x + threadIdx.x;
    if (e >= ne) return;
    int d = dst[e];
    int pos = atomicAdd(&cursor[d], 1);
    meta[pos] = make_int2(src[e] | (etype[e] << 17), __float_as_int(mask[e]));
}

// ---------------------------------------------------------------------------
// Aggregate: warp per node. Per edge: 1 uniform int2 load + 1 coalesced 128B
// gather from xr[src][etype] + 1 fma. Fused tanh.
// ---------------------------------------------------------------------------
__global__ void k_aggregate(const float* __restrict__ xr,
                            const float* __restrict__ agginit,
                            const int* __restrict__ rowptr,
                            const int2* __restrict__ meta,
                            float* __restrict__ h, int nn)
{
    const int lane = threadIdx.x & 31;
    const int w = (blockIdx.x * blockDim.x + threadIdx.x) >> 5;
    if (w >= nn) return;
    float acc = agginit[(long)w * 32 + lane];
    int i = rowptr[w];
    const int end = rowptr[w + 1];
    for (; i + 4 <= end; i += 4) {
        int2 m0 = __ldg(&meta[i]);
        int2 m1 = __ldg(&meta[i + 1]);
        int2 m2 = __ldg(&meta[i + 2]);
        int2 m3 = __ldg(&meta[i + 3]);
        float v0 = __ldg(&xr[(long)((m0.x & 0x1FFFF) * 5 + (m0.x >> 17)) * 32 + lane]);
        float v1 = __ldg(&xr[(long)((m1.x & 0x1FFFF) * 5 + (m1.x >> 17)) * 32 + lane]);
        float v2 = __ldg(&xr[(long)((m2.x & 0x1FFFF) * 5 + (m2.x >> 17)) * 32 + lane]);
        float v3 = __ldg(&xr[(long)((m3.x & 0x1FFFF) * 5 + (m3.x >> 17)) * 32 + lane]);
        acc = fmaf(__int_as_float(m0.y), v0, acc);
        acc = fmaf(__int_as_float(m1.y), v1, acc);
        acc = fmaf(__int_as_float(m2.y), v2, acc);
        acc = fmaf(__int_as_float(m3.y), v3, acc);
    }
    for (; i < end; i++) {
        int2 md = __ldg(&meta[i]);
        float v = __ldg(&xr[(long)((md.x & 0x1FFFF) * 5 + (md.x >> 17)) * 32 + lane]);
        acc = fmaf(__int_as_float(md.y), v, acc);
    }
    h[(long)w * 32 + lane] = tanhf(acc);
}

// ---------------------------------------------------------------------------
#define PPB 32
__global__ void head_kernel(const float* __restrict__ h1,
                            const float* __restrict__ h2,
                            const float* __restrict__ h3,
                            const int* __restrict__ users,
                            const int* __restrict__ items,
                            const float* __restrict__ w1,
                            const float* __restrict__ bw1,
                            const float* __restrict__ w2,
                            const float* __restrict__ bw2,
                            float* __restrict__ out,
                            int npairs)
{
    extern __shared__ float sm[];
    float* w1s = sm;
    float* feats = sm + 24576;
    const int tid = threadIdx.x;

    for (int idx = tid; idx < 24576; idx += 128) w1s[idx] = w1[idx];
    const float bb = bw1[tid];
    const float wv2 = w2[tid];
    const float b2v = bw2[0];
    __shared__ float red[4];
    __syncthreads();

    const int pend = min((blockIdx.x + 1) * PPB, npairs);
    for (int p = blockIdx.x * PPB; p < pend; p++) {
        if (tid < 96) {
            int u = __ldg(&users[p]);
            int it = __ldg(&items[p]);
            int o = tid & 31;
            const float* hu = (tid < 32) ? h1 : (tid < 64) ? h2 : h3;
            feats[tid] = hu[(long)u * 32 + o];
            feats[96 + tid] = hu[(long)it * 32 + o];
        }
        __syncthreads();
        float acc = bb;
#pragma unroll 16
        for (int k = 0; k < 192; k++)
            acc = fmaf(feats[k], w1s[k * 128 + tid], acc);
        float hv = fmaxf(acc, 0.f) * wv2;
#pragma unroll
        for (int off = 16; off; off >>= 1) hv += __shfl_down_sync(0xFFFFFFFFu, hv, off);
        if ((tid & 31) == 0) red[tid >> 5] = hv;
        __syncthreads();
        if (tid == 0) out[p] = red[0] + red[1] + red[2] + red[3] + b2v;
        __syncthreads();
    }
}

// ---------------------------------------------------------------------------
extern "C" void kernel_launch(void* const* d_in, const int* in_sizes, int n_in,
                              void* d_out, int out_size)
{
    const float* x     = (const float*)d_in[0];
    const float* emask = (const float*)d_in[1];
    const int*   etype = (const int*)d_in[2];
    const int*   src   = (const int*)d_in[3];
    const int*   dst   = (const int*)d_in[4];
    const int*   users = (const int*)d_in[5];
    const int*   items = (const int*)d_in[6];
    const float* V1    = (const float*)d_in[7];
    const float* comp1 = (const float*)d_in[8];
    const float* loop1 = (const float*)d_in[9];
    const float* b1    = (const float*)d_in[10];
    const float* V2    = (const float*)d_in[11];
    const float* comp2 = (const float*)d_in[12];
    const float* loop2 = (const float*)d_in[13];
    const float* b2    = (const float*)d_in[14];
    const float* V3    = (const float*)d_in[15];
    const float* comp3 = (const float*)d_in[16];
    const float* loop3 = (const float*)d_in[17];
    const float* b3    = (const float*)d_in[18];
    const float* w1    = (const float*)d_in[19];
    const float* bw1   = (const float*)d_in[20];
    const float* w2    = (const float*)d_in[21];
    const float* bw2   = (const float*)d_in[22];
    float* out = (float*)d_out;

    float *xr, *agg, *h1, *h2, *h3;
    int *deg, *bsum, *rowptr, *cursor;
    int2* meta;
    cudaGetSymbolAddress((void**)&xr,     g_xr);
    cudaGetSymbolAddress((void**)&agg,    g_agg);
    cudaGetSymbolAddress((void**)&h1,     g_h1);
    cudaGetSymbolAddress((void**)&h2,     g_h2);
    cudaGetSymbolAddress((void**)&h3,     g_h3);
    cudaGetSymbolAddress((void**)&deg,    g_deg);
    cudaGetSymbolAddress((void**)&bsum,   g_bsum);
    cudaGetSymbolAddress((void**)&rowptr, g_rowptr);
    cudaGetSymbolAddress((void**)&cursor, g_cursor);
    cudaGetSymbolAddress((void**)&meta,   g_meta);

    const int smem_hd = (24576 + 192) * 4;
    cudaFuncSetAttribute(transform_mma<INF>, cudaFuncAttributeMaxDynamicSharedMemorySize, TSMEM);
    cudaFuncSetAttribute(transform_mma<HID>, cudaFuncAttributeMaxDynamicSharedMemorySize, TSMEM);
    cudaFuncSetAttribute(head_kernel, cudaFuncAttributeMaxDynamicSharedMemorySize, smem_hd);

    const int tgrid = (NN + 127) / 128;        // 782
    const int agrid = (NN * 32 + 255) / 256;   // 12500

    // CSR build (reused by all 3 layers)
    k_zero<<<(NN + 255) / 256, 256>>>(deg, NN);
    k_hist<<<(NE + 255) / 256, 256>>>(dst, deg, NE);
    k_blocksum<<<NB, SCAN_BS>>>(deg, bsum, NN);
    k_scantop<<<1, 128>>>(bsum, NB, rowptr + NN);
    k_scanapply<<<NB, SCAN_BS>>>(deg, bsum, rowptr, cursor, NN);
    k_scatter<<<(NE + 255) / 256, 256>>>(src, dst, etype, emask, cursor, meta, NE);

    // Layer 1
    transform_mma<INF><<<tgrid, 256, TSMEM>>>(x, V1, loop1, b1, comp1, xr, agg, NN);
    k_aggregate<<<agrid, 256>>>(xr, agg, rowptr, meta, h1, NN);
    // Layer 2
    transform_mma<HID><<<tgrid, 256, TSMEM>>>(h1, V2, loop2, b2, comp2, xr, agg, NN);
    k_aggregate<<<agrid, 256>>>(xr, agg, rowptr, meta, h2, NN);
    // Layer 3
    transform_mma<HID><<<tgrid, 256, TSMEM>>>(h2, V3, loop3, b3, comp3, xr, agg, NN);
    k_aggregate<<<agrid, 256>>>(xr, agg, rowptr, meta, h3, NN);
    // Head
    head_kernel<<<(NPAIRS + PPB - 1) / PPB, 128, smem_hd>>>(
        h1, h2, h3, users, items, w1, bw1, w2, bw2, out, NPAIRS);
}

// round 6
// speedup vs baseline: 1.1405x; 1.1405x over previous
#include <cuda_runtime.h>
#include <math.h>

#define NN 100000
#define NE 1600000
#define INF 128
#define HID 32
#define NPAIRS 4096
#define SCAN_BS 1024
#define NB ((NN + SCAN_BS - 1) / SCAN_BS)   // 98

// scratch (device globals)
__device__ unsigned g_xbq[NN * 32];    // packed int16 pair {q0,q1} per (node,o) — 12.8MB
__device__ float    g_s[NN];           // per-node decode scale
__device__ float    g_t[NE];           // per-edge scalar mask*s[src] (per layer)
__device__ float    g_agg[NN * 32];    // agg init (loop term + bias)
__device__ float    g_h1[NN * 32];
__device__ float    g_h2[NN * 32];
__device__ float    g_h3[NN * 32];
__device__ int      g_deg[NN];
__device__ int      g_bsum[NB + 1];
__device__ int      g_rowptr[NN + 1];
__device__ int      g_cursor[NN];
__device__ int2     g_meta[NE];        // {src | etype<<17, mask_bits} grouped by dst

// ---------------------------------------------------------------------------
// Split-TF32 tensor-core transform.
// out96[n][j] = sum_d x[n][d]*Wall[d][j]  (j<64: basis b=j>>5,o=j&31; j>=64: loop)
// Epilogue: per-node max -> scale s[n]; xbq[n][o] = pack(int16(v0*k), int16(v1*k));
//           agg[n][o] = out[64+o] + bias[o]
// ---------------------------------------------------------------------------
#define XS_STRIDE 36
#define WS_STRIDE 100
#define OS_STRIDE 104
#define XS_BYTES  (128 * XS_STRIDE * 8)           // 36864
#define WS_BYTES  (32 * WS_STRIDE * 8)            // 25600
#define TSMEM     (XS_BYTES + WS_BYTES)           // 62464

__device__ __forceinline__ unsigned f2tf(float f) {
    unsigned r; asm("cvt.rna.tf32.f32 %0, %1;" : "=r"(r) : "f"(f)); return r;
}
__device__ __forceinline__ void mma8(float* c, const unsigned* a, const unsigned* b) {
    asm volatile("mma.sync.aligned.m16n8k8.row.col.f32.tf32.tf32.f32 "
                 "{%0,%1,%2,%3}, {%4,%5,%6,%7}, {%8,%9}, {%0,%1,%2,%3};"
                 : "+f"(c[0]), "+f"(c[1]), "+f"(c[2]), "+f"(c[3])
                 : "r"(a[0]), "r"(a[1]), "r"(a[2]), "r"(a[3]), "r"(b[0]), "r"(b[1]));
}

template <int DIN>
__global__ __launch_bounds__(256, 2)
void transform_mma(const float* __restrict__ xin,
                   const float* __restrict__ V,       // [2][DIN][32]
                   const float* __restrict__ loopw,   // [DIN][32]
                   const float* __restrict__ bias,    // [32]
                   unsigned* __restrict__ xbq,        // [NN][32]
                   float* __restrict__ sarr,          // [NN]
                   float* __restrict__ agg,           // [NN][32]
                   int nnodes)
{
    extern __shared__ char smraw[];
    float2* xs = (float2*)smraw;                 // [128][XS_STRIDE] {hi,lo}
    float2* ws = (float2*)(smraw + XS_BYTES);    // [32][WS_STRIDE]  {hi,lo}
    float*  outs = (float*)smraw;                // reused after compute

    const int tid = threadIdx.x;
    const int lane = tid & 31, wid = tid >> 5;
    const int warpM = wid & 3, warpN = wid >> 2;
    const int gid = lane >> 2, tig = lane & 3;
    const int base = blockIdx.x * 128;

    float c[2][6][4];
#pragma unroll
    for (int mt = 0; mt < 2; mt++)
#pragma unroll
        for (int nt = 0; nt < 6; nt++)
#pragma unroll
            for (int q = 0; q < 4; q++) c[mt][nt][q] = 0.f;

    const int NCHUNK = DIN / 32;
#pragma unroll 1
    for (int ch = 0; ch < NCHUNK; ch++) {
        const int kbase = ch * 32;
        if (ch) __syncthreads();
        for (int idx = tid; idx < 128 * 32; idx += 256) {
            int row = idx >> 5, col = idx & 31;
            int node = base + row;
            float v = (node < nnodes) ? xin[(long)node * DIN + kbase + col] : 0.f;
            unsigned hb = f2tf(v);
            float hf = __uint_as_float(hb);
            unsigned lb = f2tf(v - hf);
            xs[row * XS_STRIDE + col] = make_float2(hf, __uint_as_float(lb));
        }
        for (int idx = tid; idx < 32 * 96; idx += 256) {
            int k = idx / 96, j = idx - k * 96;
            int d = kbase + k;
            float w = (j < 64) ? V[(j >> 5) * DIN * 32 + d * 32 + (j & 31)]
                               : loopw[d * 32 + (j - 64)];
            unsigned hb = f2tf(w);
            float hf = __uint_as_float(hb);
            unsigned lb = f2tf(w - hf);
            ws[k * WS_STRIDE + j] = make_float2(hf, __uint_as_float(lb));
        }
        __syncthreads();

#pragma unroll
        for (int ks = 0; ks < 32; ks += 8) {
            unsigned ahi[2][4], alo[2][4];
#pragma unroll
            for (int mt = 0; mt < 2; mt++) {
                int r0 = warpM * 32 + mt * 16 + gid;
                float2 a0 = xs[(r0    ) * XS_STRIDE + ks + tig];
                float2 a1 = xs[(r0 + 8) * XS_STRIDE + ks + tig];
                float2 a2 = xs[(r0    ) * XS_STRIDE + ks + tig + 4];
                float2 a3 = xs[(r0 + 8) * XS_STRIDE + ks + tig + 4];
                ahi[mt][0] = __float_as_uint(a0.x); alo[mt][0] = __float_as_uint(a0.y);
                ahi[mt][1] = __float_as_uint(a1.x); alo[mt][1] = __float_as_uint(a1.y);
                ahi[mt][2] = __float_as_uint(a2.x); alo[mt][2] = __float_as_uint(a2.y);
                ahi[mt][3] = __float_as_uint(a3.x); alo[mt][3] = __float_as_uint(a3.y);
            }
            unsigned bhi[6][2], blo[6][2];
#pragma unroll
            for (int nt = 0; nt < 6; nt++) {
                int n = warpN * 48 + nt * 8 + gid;
                float2 b0 = ws[(ks + tig    ) * WS_STRIDE + n];
                float2 b1 = ws[(ks + tig + 4) * WS_STRIDE + n];
                bhi[nt][0] = __float_as_uint(b0.x); blo[nt][0] = __float_as_uint(b0.y);
                bhi[nt][1] = __float_as_uint(b1.x); blo[nt][1] = __float_as_uint(b1.y);
            }
#pragma unroll
            for (int mt = 0; mt < 2; mt++)
#pragma unroll
                for (int nt = 0; nt < 6; nt++) {
                    mma8(c[mt][nt], ahi[mt], bhi[nt]);
                    mma8(c[mt][nt], ahi[mt], blo[nt]);
                    mma8(c[mt][nt], alo[mt], bhi[nt]);
                }
        }
    }
    __syncthreads();   // compute smem dead; reuse as outs

#pragma unroll
    for (int mt = 0; mt < 2; mt++)
#pragma unroll
        for (int nt = 0; nt < 6; nt++) {
            int r0 = warpM * 32 + mt * 16 + gid;
            int c0 = warpN * 48 + nt * 8 + tig * 2;
            outs[(r0    ) * OS_STRIDE + c0    ] = c[mt][nt][0];
            outs[(r0    ) * OS_STRIDE + c0 + 1] = c[mt][nt][1];
            outs[(r0 + 8) * OS_STRIDE + c0    ] = c[mt][nt][2];
            outs[(r0 + 8) * OS_STRIDE + c0 + 1] = c[mt][nt][3];
        }
    __syncthreads();

    // Epilogue: per-row (node) max -> scale; quantize basis pair; agg init.
    // Each warp iteration handles exactly one row (lane == o).
    for (int idx = tid; idx < 128 * 32; idx += 256) {
        int row = idx >> 5, o = idx & 31;
        int node = base + row;
        float v0 = outs[row * OS_STRIDE + o];
        float v1 = outs[row * OS_STRIDE + 32 + o];
        float m = fmaxf(fabsf(v0), fabsf(v1));
#pragma unroll
        for (int off = 16; off; off >>= 1)
            m = fmaxf(m, __shfl_xor_sync(0xFFFFFFFFu, m, off));
        float k = (m > 1e-20f) ? 32767.0f / m : 0.f;
        int q0 = __float2int_rn(v0 * k);
        int q1 = __float2int_rn(v1 * k);
        unsigned pk = ((unsigned)q0 & 0xFFFFu) | ((unsigned)q1 << 16);
        if (node < nnodes) {
            xbq[(long)node * 32 + o] = pk;
            if (o == 0) sarr[node] = (m > 1e-20f) ? m * (1.0f / 32767.0f) : 0.f;
            agg[(long)node * 32 + o] = outs[row * OS_STRIDE + 64 + o] + bias[o];
        }
    }
}

// ------------------------ CSR build ---------------------------------------
__global__ void k_zero(int* p, int n)
{
    int i = blockIdx.x * blockDim.x + threadIdx.x;
    if (i < n) p[i] = 0;
}
__global__ void k_hist(const int* __restrict__ dst, int* __restrict__ deg, int ne)
{
    int i = blockIdx.x * blockDim.x + threadIdx.x;
    if (i < ne) atomicAdd(&deg[dst[i]], 1);
}
__global__ void k_blocksum(const int* __restrict__ deg, int* __restrict__ bsum, int n)
{
    __shared__ int wsum[32];
    int i = blockIdx.x * SCAN_BS + threadIdx.x;
    int v = (i < n) ? deg[i] : 0;
#pragma unroll
    for (int o = 16; o; o >>= 1) v += __shfl_down_sync(0xFFFFFFFFu, v, o);
    int lane = threadIdx.x & 31, wid = threadIdx.x >> 5;
    if (lane == 0) wsum[wid] = v;
    __syncthreads();
    if (wid == 0) {
        int x = wsum[lane];
#pragma unroll
        for (int o = 16; o; o >>= 1) x += __shfl_down_sync(0xFFFFFFFFu, x, o);
        if (lane == 0) bsum[blockIdx.x] = x;
    }
}
__global__ void k_scantop(int* __restrict__ bsum, int nb, int* __restrict__ rowptr_end)
{
    __shared__ int s[128];
    int t = threadIdx.x;
    int v = (t < nb) ? bsum[t] : 0;
    s[t] = v;
    __syncthreads();
#pragma unroll
    for (int o = 1; o < 128; o <<= 1) {
        int y = (t >= o) ? s[t - o] : 0;
        __syncthreads();
        s[t] += y;
        __syncthreads();
    }
    if (t < nb) bsum[t] = s[t] - v;
    if (t == 127) *rowptr_end = s[127];
}
__global__ void k_scanapply(const int* __restrict__ deg, const int* __restrict__ bsum,
                            int* __restrict__ rowptr, int* __restrict__ cursor, int n)
{
    __shared__ int wsum[32];
    int i = blockIdx.x * SCAN_BS + threadIdx.x;
    int v = (i < n) ? deg[i] : 0;
    int lane = threadIdx.x & 31, wid = threadIdx.x >> 5;
    unsigned fm = 0xFFFFFFFFu;
    int x = v;
#pragma unroll
    for (int o = 1; o < 32; o <<= 1) {
        int y = __shfl_up_sync(fm, x, o);
        if (lane >= o) x += y;
    }
    if (lane == 31) wsum[wid] = x;
    __syncthreads();
    if (wid == 0) {
        int w = wsum[lane];
        int wx = w;
#pragma unroll
        for (int o = 1; o < 32; o <<= 1) {
            int y = __shfl_up_sync(fm, wx, o);
            if (lane >= o) wx += y;
        }
        wsum[lane] = wx - w;
    }
    __syncthreads();
    int excl = (x - v) + wsum[wid] + bsum[blockIdx.x];
    if (i < n) { rowptr[i] = excl; cursor[i] = excl; }
}
__global__ void k_scatter(const int* __restrict__ src, const int* __restrict__ dst,
                          const int* __restrict__ etype, const float* __restrict__ mask,
                          int* __restrict__ cursor, int2* __restrict__ meta, int ne)
{
    int e = blockIdx.x * blockDim.x + threadIdx.x;
    if (e >= ne) return;
    int d = dst[e];
    int pos = atomicAdd(&cursor[d], 1);
    meta[pos] = make_int2(src[e] | (etype[e] << 17), __float_as_int(mask[e]));
}

// Per-layer edge scalar: t[e] = mask_e * s[src_e]  (s is 400KB -> cache-resident)
__global__ void k_edgescale(const int2* __restrict__ meta, const float* __restrict__ sarr,
                            float* __restrict__ t, int ne)
{
    int i = blockIdx.x * blockDim.x + threadIdx.x;
    if (i >= ne) return;
    int2 md = meta[i];
    t[i] = __int_as_float(md.y) * __ldg(&sarr[md.x & 0x1FFFF]);
}

// ---------------------------------------------------------------------------
// Aggregate: warp per node. Per edge: uniform meta.x + uniform t + ONE 128B
// gather of packed int16 pairs. msg = t*(c0[r]*q0 + c1[r]*q1). Fused tanh.
// ---------------------------------------------------------------------------
__global__ void k_aggregate(const unsigned* __restrict__ xbq,
                            const float* __restrict__ agginit,
                            const int* __restrict__ rowptr,
                            const int2* __restrict__ meta,
                            const float* __restrict__ t,
                            const float* __restrict__ comp,  // [5][2]
                            float* __restrict__ h, int nn)
{
    __shared__ float cl[16];
    if (threadIdx.x < 10) cl[threadIdx.x] = comp[threadIdx.x];
    __syncthreads();
    const int lane = threadIdx.x & 31;
    const int w = (blockIdx.x * blockDim.x + threadIdx.x) >> 5;
    if (w >= nn) return;
    float acc = agginit[(long)w * 32 + lane];
    int i = rowptr[w];
    const int end = rowptr[w + 1];
    for (; i + 4 <= end; i += 4) {
        int2 m0 = __ldg(&meta[i]);
        int2 m1 = __ldg(&meta[i + 1]);
        int2 m2 = __ldg(&meta[i + 2]);
        int2 m3 = __ldg(&meta[i + 3]);
        float t0 = __ldg(&t[i]),     t1 = __ldg(&t[i + 1]);
        float t2 = __ldg(&t[i + 2]), t3 = __ldg(&t[i + 3]);
        unsigned u0 = __ldg(&xbq[(long)(m0.x & 0x1FFFF) * 32 + lane]);
        unsigned u1 = __ldg(&xbq[(long)(m1.x & 0x1FFFF) * 32 + lane]);
        unsigned u2 = __ldg(&xbq[(long)(m2.x & 0x1FFFF) * 32 + lane]);
        unsigned u3 = __ldg(&xbq[(long)(m3.x & 0x1FFFF) * 32 + lane]);
        int r0 = (m0.x >> 17) * 2, r1 = (m1.x >> 17) * 2;
        int r2 = (m2.x >> 17) * 2, r3 = (m3.x >> 17) * 2;
        float a0 = (float)((int)(u0 << 16) >> 16), b0 = (float)((int)u0 >> 16);
        float a1 = (float)((int)(u1 << 16) >> 16), b1 = (float)((int)u1 >> 16);
        float a2 = (float)((int)(u2 << 16) >> 16), b2 = (float)((int)u2 >> 16);
        float a3 = (float)((int)(u3 << 16) >> 16), b3 = (float)((int)u3 >> 16);
        acc = fmaf(t0, fmaf(cl[r0], a0, cl[r0 + 1] * b0), acc);
        acc = fmaf(t1, fmaf(cl[r1], a1, cl[r1 + 1] * b1), acc);
        acc = fmaf(t2, fmaf(cl[r2], a2, cl[r2 + 1] * b2), acc);
        acc = fmaf(t3, fmaf(cl[r3], a3, cl[r3 + 1] * b3), acc);
    }
    for (; i < end; i++) {
        int2 md = __ldg(&meta[i]);
        float tv = __ldg(&t[i]);
        unsigned u = __ldg(&xbq[(long)(md.x & 0x1FFFF) * 32 + lane]);
        int r = (md.x >> 17) * 2;
        float a = (float)((int)(u << 16) >> 16), b = (float)((int)u >> 16);
        acc = fmaf(tv, fmaf(cl[r], a, cl[r + 1] * b), acc);
    }
    h[(long)w * 32 + lane] = tanhf(acc);
}

// ---------------------------------------------------------------------------
#define PPB 32
__global__ void head_kernel(const float* __restrict__ h1,
                            const float* __restrict__ h2,
                            const float* __restrict__ h3,
                            const int* __restrict__ users,
                            const int* __restrict__ items,
                            const float* __restrict__ w1,
                            const float* __restrict__ bw1,
                            const float* __restrict__ w2,
                            const float* __restrict__ bw2,
                            float* __restrict__ out,
                            int npairs)
{
    extern __shared__ float sm[];
    float* w1s = sm;
    float* feats = sm + 24576;
    const int tid = threadIdx.x;

    for (int idx = tid; idx < 24576; idx += 128) w1s[idx] = w1[idx];
    const float bb = bw1[tid];
    const float wv2 = w2[tid];
    const float b2v = bw2[0];
    __shared__ float red[4];
    __syncthreads();

    const int pend = min((blockIdx.x + 1) * PPB, npairs);
    for (int p = blockIdx.x * PPB; p < pend; p++) {
        if (tid < 96) {
            int u = __ldg(&users[p]);
            int it = __ldg(&items[p]);
            int o = tid & 31;
            const float* hu = (tid < 32) ? h1 : (tid < 64) ? h2 : h3;
            feats[tid] = hu[(long)u * 32 + o];
            feats[96 + tid] = hu[(long)it * 32 + o];
        }
        __syncthreads();
        float acc = bb;
#pragma unroll 16
        for (int k = 0; k < 192; k++)
            acc = fmaf(feats[k], w1s[k * 128 + tid], acc);
        float hv = fmaxf(acc, 0.f) * wv2;
#pragma unroll
        for (int off = 16; off; off >>= 1) hv += __shfl_down_sync(0xFFFFFFFFu, hv, off);
        if ((tid & 31) == 0) red[tid >> 5] = hv;
        __syncthreads();
        if (tid == 0) out[p] = red[0] + red[1] + red[2] + red[3] + b2v;
        __syncthreads();
    }
}

// ---------------------------------------------------------------------------
extern "C" void kernel_launch(void* const* d_in, const int* in_sizes, int n_in,
                              void* d_out, int out_size)
{
    const float* x     = (const float*)d_in[0];
    const float* emask = (const float*)d_in[1];
    const int*   etype = (const int*)d_in[2];
    const int*   src   = (const int*)d_in[3];
    const int*   dst   = (const int*)d_in[4];
    const int*   users = (const int*)d_in[5];
    const int*   items = (const int*)d_in[6];
    const float* V1    = (const float*)d_in[7];
    const float* comp1 = (const float*)d_in[8];
    const float* loop1 = (const float*)d_in[9];
    const float* b1    = (const float*)d_in[10];
    const float* V2    = (const float*)d_in[11];
    const float* comp2 = (const float*)d_in[12];
    const float* loop2 = (const float*)d_in[13];
    const float* b2    = (const float*)d_in[14];
    const float* V3    = (const float*)d_in[15];
    const float* comp3 = (const float*)d_in[16];
    const float* loop3 = (const float*)d_in[17];
    const float* b3    = (const float*)d_in[18];
    const float* w1    = (const float*)d_in[19];
    const float* bw1   = (const float*)d_in[20];
    const float* w2    = (const float*)d_in[21];
    const float* bw2   = (const float*)d_in[22];
    float* out = (float*)d_out;

    unsigned* xbq;
    float *sarr, *tarr, *agg, *h1, *h2, *h3;
    int *deg, *bsum, *rowptr, *cursor;
    int2* meta;
    cudaGetSymbolAddress((void**)&xbq,    g_xbq);
    cudaGetSymbolAddress((void**)&sarr,   g_s);
    cudaGetSymbolAddress((void**)&tarr,   g_t);
    cudaGetSymbolAddress((void**)&agg,    g_agg);
    cudaGetSymbolAddress((void**)&h1,     g_h1);
    cudaGetSymbolAddress((void**)&h2,     g_h2);
    cudaGetSymbolAddress((void**)&h3,     g_h3);
    cudaGetSymbolAddress((void**)&deg,    g_deg);
    cudaGetSymbolAddress((void**)&bsum,   g_bsum);
    cudaGetSymbolAddress((void**)&rowptr, g_rowptr);
    cudaGetSymbolAddress((void**)&cursor, g_cursor);
    cudaGetSymbolAddress((void**)&meta,   g_meta);

    const int smem_hd = (24576 + 192) * 4;
    cudaFuncSetAttribute(transform_mma<INF>, cudaFuncAttributeMaxDynamicSharedMemorySize, TSMEM);
    cudaFuncSetAttribute(transform_mma<HID>, cudaFuncAttributeMaxDynamicSharedMemorySize, TSMEM);
    cudaFuncSetAttribute(head_kernel, cudaFuncAttributeMaxDynamicSharedMemorySize, smem_hd);

    const int tgrid = (NN + 127) / 128;        // 782
    const int agrid = (NN * 32 + 255) / 256;   // 12500
    const int egrid = (NE + 255) / 256;

    // CSR build; transform<128> placed at launch index 3 so ncu captures it.
    k_zero<<<(NN + 255) / 256, 256>>>(deg, NN);
    k_hist<<<egrid, 256>>>(dst, deg, NE);
    k_blocksum<<<NB, SCAN_BS>>>(deg, bsum, NN);
    transform_mma<INF><<<tgrid, 256, TSMEM>>>(x, V1, loop1, b1, xbq, sarr, agg, NN);
    k_scantop<<<1, 128>>>(bsum, NB, rowptr + NN);
    k_scanapply<<<NB, SCAN_BS>>>(deg, bsum, rowptr, cursor, NN);
    k_scatter<<<egrid, 256>>>(src, dst, etype, emask, cursor, meta, NE);

    // Layer 1
    k_edgescale<<<egrid, 256>>>(meta, sarr, tarr, NE);
    k_aggregate<<<agrid, 256>>>(xbq, agg, rowptr, meta, tarr, comp1, h1, NN);
    // Layer 2
    transform_mma<HID><<<tgrid, 256, TSMEM>>>(h1, V2, loop2, b2, xbq, sarr, agg, NN);
    k_edgescale<<<egrid, 256>>>(meta, sarr, tarr, NE);
    k_aggregate<<<agrid, 256>>>(xbq, agg, rowptr, meta, tarr, comp2, h2, NN);
    // Layer 3
    transform_mma<HID><<<tgrid, 256, TSMEM>>>(h2, V3, loop3, b3, xbq, sarr, agg, NN);
    k_edgescale<<<egrid, 256>>>(meta, sarr, tarr, NE);
    k_aggregate<<<agrid, 256>>>(xbq, agg, rowptr, meta, tarr, comp3, h3, NN);
    // Head
    head_kernel<<<(NPAIRS + PPB - 1) / PPB, 128, smem_hd>>>(
        h1, h2, h3, users, items, w1, bw1, w2, bw2, out, NPAIRS);
}

// round 7
// speedup vs baseline: 1.2405x; 1.0877x over previous
#include <cuda_runtime.h>
#include <math.h>

#define NN 100000
#define NE 1600000
#define INF 128
#define HID 32
#define NPAIRS 4096
#define SCAN_BS 1024
#define NB ((NN + SCAN_BS - 1) / SCAN_BS)   // 98

// scratch (device globals)
__device__ unsigned g_xbq[NN * 32];    // packed int16 pair {q0,q1} per (node,o) — 12.8MB
__device__ float    g_s[NN];           // per-node decode scale
__device__ float    g_agg[NN * 32];    // agg init (loop term + bias)
__device__ float    g_h1[NN * 32];
__device__ float    g_h2[NN * 32];
__device__ float    g_h3[NN * 32];
__device__ int      g_deg[NN];
__device__ int      g_bsum[NB + 1];
__device__ int      g_rowptr[NN + 1];
__device__ int      g_cursor[NN];
__device__ int2     g_meta[NE];        // {src | etype<<17, mask_bits} grouped by dst
__device__ float2   g_wsp1[INF * 96];  // pre-split tf32 {hi,lo} weights, layer 1
__device__ float2   g_wsp2[HID * 96];
__device__ float2   g_wsp3[HID * 96];

// ---------------------------------------------------------------------------
#define XS_STRIDE 36
#define WS_STRIDE 100
#define OS_STRIDE 104
#define XS_BYTES  (128 * XS_STRIDE * 8)           // 36864
#define WS_BYTES  (32 * WS_STRIDE * 8)            // 25600
#define TSMEM     (XS_BYTES + WS_BYTES)           // 62464

__device__ __forceinline__ void mma8(float* c, const unsigned* a, const unsigned* b) {
    asm volatile("mma.sync.aligned.m16n8k8.row.col.f32.tf32.tf32.f32 "
                 "{%0,%1,%2,%3}, {%4,%5,%6,%7}, {%8,%9}, {%0,%1,%2,%3};"
                 : "+f"(c[0]), "+f"(c[1]), "+f"(c[2]), "+f"(c[3])
                 : "r"(a[0]), "r"(a[1]), "r"(a[2]), "r"(a[3]), "r"(b[0]), "r"(b[1]));
}
__device__ __forceinline__ float2 msplit(float v) {
    float hi = __uint_as_float(__float_as_uint(v) & 0xFFFFE000u);
    return make_float2(hi, v - hi);
}

// Pre-split weights: wsp[d*96+j] = {hi,lo} of Wall[d][j]
__global__ void k_wsplit(const float* __restrict__ V, const float* __restrict__ loopw,
                         float2* __restrict__ wsp, int DIN)
{
    int idx = blockIdx.x * blockDim.x + threadIdx.x;
    if (idx >= DIN * 96) return;
    int d = idx / 96, j = idx - d * 96;
    float w = (j < 64) ? V[(j >> 5) * DIN * 32 + d * 32 + (j & 31)]
                       : loopw[d * 32 + (j - 64)];
    wsp[idx] = msplit(w);
}

// ---------------------------------------------------------------------------
// Split-TF32 tensor-core transform (W pre-split; x mask-split).
// out96[n][j] = sum_d x[n][d]*Wall[d][j]  (j<64: basis; j>=64: loop)
// Epilogue: per-node scale s[n]; xbq packed int16 pair; agg init = loop + bias
// ---------------------------------------------------------------------------
template <int DIN>
__global__ __launch_bounds__(256, 2)
void transform_mma(const float* __restrict__ xin,
                   const float2* __restrict__ wsp,    // [DIN][96] pre-split
                   const float* __restrict__ bias,
                   unsigned* __restrict__ xbq,
                   float* __restrict__ sarr,
                   float* __restrict__ agg,
                   int nnodes)
{
    extern __shared__ char smraw[];
    float2* xs = (float2*)smraw;                 // [128][XS_STRIDE] {hi,lo}
    float2* ws = (float2*)(smraw + XS_BYTES);    // [32][WS_STRIDE]  {hi,lo}
    float*  outs = (float*)smraw;                // reused after compute

    const int tid = threadIdx.x;
    const int lane = tid & 31, wid = tid >> 5;
    const int warpM = wid & 3, warpN = wid >> 2;
    const int gid = lane >> 2, tig = lane & 3;
    const int base = blockIdx.x * 128;

    float c[2][6][4];
#pragma unroll
    for (int mt = 0; mt < 2; mt++)
#pragma unroll
        for (int nt = 0; nt < 6; nt++)
#pragma unroll
            for (int q = 0; q < 4; q++) c[mt][nt][q] = 0.f;

    const int NCHUNK = DIN / 32;
#pragma unroll 1
    for (int ch = 0; ch < NCHUNK; ch++) {
        const int kbase = ch * 32;
        if (ch) __syncthreads();
        // stage x chunk: 128 rows x 32 cols via float4 + mask split
        for (int idx = tid; idx < 128 * 8; idx += 256) {
            int row = idx >> 3, c4 = (idx & 7) * 4;
            int node = base + row;
            float4 v = (node < nnodes)
                ? *(const float4*)(xin + (long)node * DIN + kbase + c4)
                : make_float4(0.f, 0.f, 0.f, 0.f);
            float2 p0 = msplit(v.x), p1 = msplit(v.y);
            float2 p2 = msplit(v.z), p3 = msplit(v.w);
            float4* dst = (float4*)&xs[row * XS_STRIDE + c4];
            dst[0] = make_float4(p0.x, p0.y, p1.x, p1.y);
            dst[1] = make_float4(p2.x, p2.y, p3.x, p3.y);
        }
        // stage W chunk (pre-split): 32 x 96 float2, via float4 copies
        for (int idx = tid; idx < 32 * 48; idx += 256) {
            int k = idx / 48, j2 = (idx % 48) * 2;
            float4 v = *(const float4*)&wsp[(kbase + k) * 96 + j2];
            *(float4*)&ws[k * WS_STRIDE + j2] = v;
        }
        __syncthreads();

#pragma unroll
        for (int ks = 0; ks < 32; ks += 8) {
            unsigned ahi[2][4], alo[2][4];
#pragma unroll
            for (int mt = 0; mt < 2; mt++) {
                int r0 = warpM * 32 + mt * 16 + gid;
                float2 a0 = xs[(r0    ) * XS_STRIDE + ks + tig];
                float2 a1 = xs[(r0 + 8) * XS_STRIDE + ks + tig];
                float2 a2 = xs[(r0    ) * XS_STRIDE + ks + tig + 4];
                float2 a3 = xs[(r0 + 8) * XS_STRIDE + ks + tig + 4];
                ahi[mt][0] = __float_as_uint(a0.x); alo[mt][0] = __float_as_uint(a0.y);
                ahi[mt][1] = __float_as_uint(a1.x); alo[mt][1] = __float_as_uint(a1.y);
                ahi[mt][2] = __float_as_uint(a2.x); alo[mt][2] = __float_as_uint(a2.y);
                ahi[mt][3] = __float_as_uint(a3.x); alo[mt][3] = __float_as_uint(a3.y);
            }
            unsigned bhi[6][2], blo[6][2];
#pragma unroll
            for (int nt = 0; nt < 6; nt++) {
                int n = warpN * 48 + nt * 8 + gid;
                float2 b0 = ws[(ks + tig    ) * WS_STRIDE + n];
                float2 b1 = ws[(ks + tig + 4) * WS_STRIDE + n];
                bhi[nt][0] = __float_as_uint(b0.x); blo[nt][0] = __float_as_uint(b0.y);
                bhi[nt][1] = __float_as_uint(b1.x); blo[nt][1] = __float_as_uint(b1.y);
            }
#pragma unroll
            for (int mt = 0; mt < 2; mt++)
#pragma unroll
                for (int nt = 0; nt < 6; nt++) {
                    mma8(c[mt][nt], ahi[mt], bhi[nt]);
                    mma8(c[mt][nt], ahi[mt], blo[nt]);
                    mma8(c[mt][nt], alo[mt], bhi[nt]);
                }
        }
    }
    __syncthreads();   // compute smem dead; reuse as outs

#pragma unroll
    for (int mt = 0; mt < 2; mt++)
#pragma unroll
        for (int nt = 0; nt < 6; nt++) {
            int r0 = warpM * 32 + mt * 16 + gid;
            int c0 = warpN * 48 + nt * 8 + tig * 2;
            outs[(r0    ) * OS_STRIDE + c0    ] = c[mt][nt][0];
            outs[(r0    ) * OS_STRIDE + c0 + 1] = c[mt][nt][1];
            outs[(r0 + 8) * OS_STRIDE + c0    ] = c[mt][nt][2];
            outs[(r0 + 8) * OS_STRIDE + c0 + 1] = c[mt][nt][3];
        }
    __syncthreads();

    // Epilogue: per-node max -> scale; quantize basis pair; agg init.
    for (int idx = tid; idx < 128 * 32; idx += 256) {
        int row = idx >> 5, o = idx & 31;
        int node = base + row;
        float v0 = outs[row * OS_STRIDE + o];
        float v1 = outs[row * OS_STRIDE + 32 + o];
        float m = fmaxf(fabsf(v0), fabsf(v1));
#pragma unroll
        for (int off = 16; off; off >>= 1)
            m = fmaxf(m, __shfl_xor_sync(0xFFFFFFFFu, m, off));
        float k = (m > 1e-20f) ? 32767.0f / m : 0.f;
        int q0 = __float2int_rn(v0 * k);
        int q1 = __float2int_rn(v1 * k);
        unsigned pk = ((unsigned)q0 & 0xFFFFu) | ((unsigned)q1 << 16);
        if (node < nnodes) {
            xbq[(long)node * 32 + o] = pk;
            if (o == 0) sarr[node] = (m > 1e-20f) ? m * (1.0f / 32767.0f) : 0.f;
            agg[(long)node * 32 + o] = outs[row * OS_STRIDE + 64 + o] + bias[o];
        }
    }
}

// ------------------------ CSR build ---------------------------------------
__global__ void k_zero(int* p, int n)
{
    int i = blockIdx.x * blockDim.x + threadIdx.x;
    if (i < n) p[i] = 0;
}
__global__ void k_hist(const int* __restrict__ dst, int* __restrict__ deg, int ne)
{
    int i = blockIdx.x * blockDim.x + threadIdx.x;
    if (i < ne) atomicAdd(&deg[dst[i]], 1);
}
__global__ void k_blocksum(const int* __restrict__ deg, int* __restrict__ bsum, int n)
{
    __shared__ int wsum[32];
    int i = blockIdx.x * SCAN_BS + threadIdx.x;
    int v = (i < n) ? deg[i] : 0;
#pragma unroll
    for (int o = 16; o; o >>= 1) v += __shfl_down_sync(0xFFFFFFFFu, v, o);
    int lane = threadIdx.x & 31, wid = threadIdx.x >> 5;
    if (lane == 0) wsum[wid] = v;
    __syncthreads();
    if (wid == 0) {
        int x = wsum[lane];
#pragma unroll
        for (int o = 16; o; o >>= 1) x += __shfl_down_sync(0xFFFFFFFFu, x, o);
        if (lane == 0) bsum[blockIdx.x] = x;
    }
}
__global__ void k_scantop(int* __restrict__ bsum, int nb, int* __restrict__ rowptr_end)
{
    __shared__ int s[128];
    int t = threadIdx.x;
    int v = (t < nb) ? bsum[t] : 0;
    s[t] = v;
    __syncthreads();
#pragma unroll
    for (int o = 1; o < 128; o <<= 1) {
        int y = (t >= o) ? s[t - o] : 0;
        __syncthreads();
        s[t] += y;
        __syncthreads();
    }
    if (t < nb) bsum[t] = s[t] - v;
    if (t == 127) *rowptr_end = s[127];
}
__global__ void k_scanapply(const int* __restrict__ deg, const int* __restrict__ bsum,
                            int* __restrict__ rowptr, int* __restrict__ cursor, int n)
{
    __shared__ int wsum[32];
    int i = blockIdx.x * SCAN_BS + threadIdx.x;
    int v = (i < n) ? deg[i] : 0;
    int lane = threadIdx.x & 31, wid = threadIdx.x >> 5;
    unsigned fm = 0xFFFFFFFFu;
    int x = v;
#pragma unroll
    for (int o = 1; o < 32; o <<= 1) {
        int y = __shfl_up_sync(fm, x, o);
        if (lane >= o) x += y;
    }
    if (lane == 31) wsum[wid] = x;
    __syncthreads();
    if (wid == 0) {
        int w = wsum[lane];
        int wx = w;
#pragma unroll
        for (int o = 1; o < 32; o <<= 1) {
            int y = __shfl_up_sync(fm, wx, o);
            if (lane >= o) wx += y;
        }
        wsum[lane] = wx - w;
    }
    __syncthreads();
    int excl = (x - v) + wsum[wid] + bsum[blockIdx.x];
    if (i < n) { rowptr[i] = excl; cursor[i] = excl; }
}
__global__ void k_scatter(const int* __restrict__ src, const int* __restrict__ dst,
                          const int* __restrict__ etype, const float* __restrict__ mask,
                          int* __restrict__ cursor, int2* __restrict__ meta, int ne)
{
    int e = blockIdx.x * blockDim.x + threadIdx.x;
    if (e >= ne) return;
    int d = dst[e];
    int pos = atomicAdd(&cursor[d], 1);
    meta[pos] = make_int2(src[e] | (etype[e] << 17), __float_as_int(mask[e]));
}

// ---------------------------------------------------------------------------
// Aggregate: warp per node. Per edge: uniform meta + uniform s[src] broadcast
// gather + ONE 128B int16-pair gather. Fused tanh.
// ---------------------------------------------------------------------------
__global__ void k_aggregate(const unsigned* __restrict__ xbq,
                            const float* __restrict__ sarr,
                            const float* __restrict__ agginit,
                            const int* __restrict__ rowptr,
                            const int2* __restrict__ meta,
                            const float* __restrict__ comp,  // [5][2]
                            float* __restrict__ h, int nn)
{
    __shared__ float cl[16];
    if (threadIdx.x < 10) cl[threadIdx.x] = comp[threadIdx.x];
    __syncthreads();
    const int lane = threadIdx.x & 31;
    const int w = (blockIdx.x * blockDim.x + threadIdx.x) >> 5;
    if (w >= nn) return;
    float acc = agginit[(long)w * 32 + lane];
    int i = rowptr[w];
    const int end = rowptr[w + 1];
    for (; i + 4 <= end; i += 4) {
        int2 m0 = __ldg(&meta[i]);
        int2 m1 = __ldg(&meta[i + 1]);
        int2 m2 = __ldg(&meta[i + 2]);
        int2 m3 = __ldg(&meta[i + 3]);
        int s0 = m0.x & 0x1FFFF, s1 = m1.x & 0x1FFFF;
        int s2 = m2.x & 0x1FFFF, s3 = m3.x & 0x1FFFF;
        float t0 = __int_as_float(m0.y) * __ldg(&sarr[s0]);
        float t1 = __int_as_float(m1.y) * __ldg(&sarr[s1]);
        float t2 = __int_as_float(m2.y) * __ldg(&sarr[s2]);
        float t3 = __int_as_float(m3.y) * __ldg(&sarr[s3]);
        unsigned u0 = __ldg(&xbq[(long)s0 * 32 + lane]);
        unsigned u1 = __ldg(&xbq[(long)s1 * 32 + lane]);
        unsigned u2 = __ldg(&xbq[(long)s2 * 32 + lane]);
        unsigned u3 = __ldg(&xbq[(long)s3 * 32 + lane]);
        int r0 = (m0.x >> 17) * 2, r1 = (m1.x >> 17) * 2;
        int r2 = (m2.x >> 17) * 2, r3 = (m3.x >> 17) * 2;
        float a0 = (float)((int)(u0 << 16) >> 16), b0 = (float)((int)u0 >> 16);
        float a1 = (float)((int)(u1 << 16) >> 16), b1 = (float)((int)u1 >> 16);
        float a2 = (float)((int)(u2 << 16) >> 16), b2 = (float)((int)u2 >> 16);
        float a3 = (float)((int)(u3 << 16) >> 16), b3 = (float)((int)u3 >> 16);
        acc = fmaf(t0, fmaf(cl[r0], a0, cl[r0 + 1] * b0), acc);
        acc = fmaf(t1, fmaf(cl[r1], a1, cl[r1 + 1] * b1), acc);
        acc = fmaf(t2, fmaf(cl[r2], a2, cl[r2 + 1] * b2), acc);
        acc = fmaf(t3, fmaf(cl[r3], a3, cl[r3 + 1] * b3), acc);
    }
    for (; i < end; i++) {
        int2 md = __ldg(&meta[i]);
        int sidx = md.x & 0x1FFFF;
        float tv = __int_as_float(md.y) * __ldg(&sarr[sidx]);
        unsigned u = __ldg(&xbq[(long)sidx * 32 + lane]);
        int r = (md.x >> 17) * 2;
        float a = (float)((int)(u << 16) >> 16), b = (float)((int)u >> 16);
        acc = fmaf(tv, fmaf(cl[r], a, cl[r + 1] * b), acc);
    }
    h[(long)w * 32 + lane] = tanhf(acc);
}

// ---------------------------------------------------------------------------
#define PPB 32
__global__ void head_kernel(const float* __restrict__ h1,
                            const float* __restrict__ h2,
                            const float* __restrict__ h3,
                            const int* __restrict__ users,
                            const int* __restrict__ items,
                            const float* __restrict__ w1,
                            const float* __restrict__ bw1,
                            const float* __restrict__ w2,
                            const float* __restrict__ bw2,
                            float* __restrict__ out,
                            int npairs)
{
    extern __shared__ float sm[];
    float* w1s = sm;
    float* feats = sm + 24576;
    const int tid = threadIdx.x;

    for (int idx = tid; idx < 24576; idx += 128) w1s[idx] = w1[idx];
    const float bb = bw1[tid];
    const float wv2 = w2[tid];
    const float b2v = bw2[0];
    __shared__ float red[4];
    __syncthreads();

    const int pend = min((blockIdx.x + 1) * PPB, npairs);
    for (int p = blockIdx.x * PPB; p < pend; p++) {
        if (tid < 96) {
            int u = __ldg(&users[p]);
            int it = __ldg(&items[p]);
            int o = tid & 31;
            const float* hu = (tid < 32) ? h1 : (tid < 64) ? h2 : h3;
            feats[tid] = hu[(long)u * 32 + o];
            feats[96 + tid] = hu[(long)it * 32 + o];
        }
        __syncthreads();
        float acc = bb;
#pragma unroll 16
        for (int k = 0; k < 192; k++)
            acc = fmaf(feats[k], w1s[k * 128 + tid], acc);
        float hv = fmaxf(acc, 0.f) * wv2;
#pragma unroll
        for (int off = 16; off; off >>= 1) hv += __shfl_down_sync(0xFFFFFFFFu, hv, off);
        if ((tid & 31) == 0) red[tid >> 5] = hv;
        __syncthreads();
        if (tid == 0) out[p] = red[0] + red[1] + red[2] + red[3] + b2v;
        __syncthreads();
    }
}

// ---------------------------------------------------------------------------
extern "C" void kernel_launch(void* const* d_in, const int* in_sizes, int n_in,
                              void* d_out, int out_size)
{
    const float* x     = (const float*)d_in[0];
    const float* emask = (const float*)d_in[1];
    const int*   etype = (const int*)d_in[2];
    const int*   src   = (const int*)d_in[3];
    const int*   dst   = (const int*)d_in[4];
    const int*   users = (const int*)d_in[5];
    const int*   items = (const int*)d_in[6];
    const float* V1    = (const float*)d_in[7];
    const float* loop1 = (const float*)d_in[9];
    const float* b1    = (const float*)d_in[10];
    const float* comp1 = (const float*)d_in[8];
    const float* V2    = (const float*)d_in[11];
    const float* comp2 = (const float*)d_in[12];
    const float* loop2 = (const float*)d_in[13];
    const float* b2    = (const float*)d_in[14];
    const float* V3    = (const float*)d_in[15];
    const float* comp3 = (const float*)d_in[16];
    const float* loop3 = (const float*)d_in[17];
    const float* b3    = (const float*)d_in[18];
    const float* w1    = (const float*)d_in[19];
    const float* bw1   = (const float*)d_in[20];
    const float* w2    = (const float*)d_in[21];
    const float* bw2   = (const float*)d_in[22];
    float* out = (float*)d_out;

    unsigned* xbq;
    float *sarr, *agg, *h1, *h2, *h3;
    float2 *wsp1, *wsp2, *wsp3;
    int *deg, *bsum, *rowptr, *cursor;
    int2* meta;
    cudaGetSymbolAddress((void**)&xbq,    g_xbq);
    cudaGetSymbolAddress((void**)&sarr,   g_s);
    cudaGetSymbolAddress((void**)&agg,    g_agg);
    cudaGetSymbolAddress((void**)&h1,     g_h1);
    cudaGetSymbolAddress((void**)&h2,     g_h2);
    cudaGetSymbolAddress((void**)&h3,     g_h3);
    cudaGetSymbolAddress((void**)&deg,    g_deg);
    cudaGetSymbolAddress((void**)&bsum,   g_bsum);
    cudaGetSymbolAddress((void**)&rowptr, g_rowptr);
    cudaGetSymbolAddress((void**)&cursor, g_cursor);
    cudaGetSymbolAddress((void**)&meta,   g_meta);
    cudaGetSymbolAddress((void**)&wsp1,   g_wsp1);
    cudaGetSymbolAddress((void**)&wsp2,   g_wsp2);
    cudaGetSymbolAddress((void**)&wsp3,   g_wsp3);

    const int smem_hd = (24576 + 192) * 4;
    cudaFuncSetAttribute(transform_mma<INF>, cudaFuncAttributeMaxDynamicSharedMemorySize, TSMEM);
    cudaFuncSetAttribute(transform_mma<HID>, cudaFuncAttributeMaxDynamicSharedMemorySize, TSMEM);
    cudaFuncSetAttribute(head_kernel, cudaFuncAttributeMaxDynamicSharedMemorySize, smem_hd);

    const int tgrid = (NN + 127) / 128;        // 782
    const int agrid = (NN * 32 + 255) / 256;   // 12500
    const int egrid = (NE + 255) / 256;

    // Prep + CSR build; transform<128> at launch index 3 for ncu.
    k_zero<<<(NN + 255) / 256, 256>>>(deg, NN);
    k_hist<<<egrid, 256>>>(dst, deg, NE);
    k_wsplit<<<(INF * 96 + 255) / 256, 256>>>(V1, loop1, wsp1, INF);
    transform_mma<INF><<<tgrid, 256, TSMEM>>>(x, wsp1, b1, xbq, sarr, agg, NN);
    k_wsplit<<<(HID * 96 + 255) / 256, 256>>>(V2, loop2, wsp2, HID);
    k_wsplit<<<(HID * 96 + 255) / 256, 256>>>(V3, loop3, wsp3, HID);
    k_blocksum<<<NB, SCAN_BS>>>(deg, bsum, NN);
    k_scantop<<<1, 128>>>(bsum, NB, rowptr + NN);
    k_scanapply<<<NB, SCAN_BS>>>(deg, bsum, rowptr, cursor, NN);
    k_scatter<<<egrid, 256>>>(src, dst, etype, emask, cursor, meta, NE);

    // Layer 1
    k_aggregate<<<agrid, 256>>>(xbq, sarr, agg, rowptr, meta, comp1, h1, NN);
    // Layer 2
    transform_mma<HID><<<tgrid, 256, TSMEM>>>(h1, wsp2, b2, xbq, sarr, agg, NN);
    k_aggregate<<<agrid, 256>>>(xbq, sarr, agg, rowptr, meta, comp2, h2, NN);
    // Layer 3
    transform_mma<HID><<<tgrid, 256, TSMEM>>>(h2, wsp3, b3, xbq, sarr, agg, NN);
    k_aggregate<<<agrid, 256>>>(xbq, sarr, agg, rowptr, meta, comp3, h3, NN);
    // Head
    head_kernel<<<(NPAIRS + PPB - 1) / PPB, 128, smem_hd>>>(
        h1, h2, h3, users, items, w1, bw1, w2, bw2, out, NPAIRS);
}

// round 8
// speedup vs baseline: 1.3016x; 1.0493x over previous
#include <cuda_runtime.h>
#include <math.h>

#define NN 100000
#define NE 1600000
#define INF 128
#define HID 32
#define NPAIRS 4096
#define SCAN_BS 1024
#define NB ((NN + SCAN_BS - 1) / SCAN_BS)   // 98

// scratch (device globals)
__device__ unsigned g_xbq[NN * 32];    // packed int16 pair {q0,q1} per (node,o) — 12.8MB
__device__ float    g_s[NN];           // per-node decode scale
__device__ float    g_agg[NN * 32];    // agg init (loop term + bias)
__device__ float    g_h1[NN * 32];
__device__ float    g_h2[NN * 32];
__device__ float    g_h3[NN * 32];
__device__ int      g_deg[NN];
__device__ int      g_bsum[NB + 1];
__device__ int      g_rowptr[NN + 1];
__device__ int      g_cursor[NN];
__device__ int2     g_meta[NE];        // {src | etype<<17, mask_bits} grouped by dst
__device__ float2   g_wsp1[INF * 96];  // pre-split tf32 {hi,lo} weights
__device__ float2   g_wsp2[HID * 96];
__device__ float2   g_wsp3[HID * 96];

// ---------------------------------------------------------------------------
// 64-row M-tile, 8 warps: warpM in {0,1} (32 rows), warpN in {0..3} (24 cols)
// ---------------------------------------------------------------------------
#define MROWS 64
#define XS_STRIDE 36
#define WS_STRIDE 100
#define OS_STRIDE 104
#define XS_BYTES  (MROWS * XS_STRIDE * 8)         // 18432
#define WS_BYTES  (32 * WS_STRIDE * 8)            // 25600
#define TSMEM     (XS_BYTES + WS_BYTES)           // 44032 (outs 64*104*4=26624 fits)

__device__ __forceinline__ void mma8(float* c, const unsigned* a, const unsigned* b) {
    asm volatile("mma.sync.aligned.m16n8k8.row.col.f32.tf32.tf32.f32 "
                 "{%0,%1,%2,%3}, {%4,%5,%6,%7}, {%8,%9}, {%0,%1,%2,%3};"
                 : "+f"(c[0]), "+f"(c[1]), "+f"(c[2]), "+f"(c[3])
                 : "r"(a[0]), "r"(a[1]), "r"(a[2]), "r"(a[3]), "r"(b[0]), "r"(b[1]));
}
__device__ __forceinline__ float2 msplit(float v) {
    float hi = __uint_as_float(__float_as_uint(v) & 0xFFFFE000u);
    return make_float2(hi, v - hi);
}

// Pre-split weights: wsp[d*96+j] = {hi,lo} of Wall[d][j]
__global__ void k_wsplit(const float* __restrict__ V, const float* __restrict__ loopw,
                         float2* __restrict__ wsp, int DIN)
{
    int idx = blockIdx.x * blockDim.x + threadIdx.x;
    if (idx >= DIN * 96) return;
    int d = idx / 96, j = idx - d * 96;
    float w = (j < 64) ? V[(j >> 5) * DIN * 32 + d * 32 + (j & 31)]
                       : loopw[d * 32 + (j - 64)];
    wsp[idx] = msplit(w);
}

// ---------------------------------------------------------------------------
// Split-TF32 tensor-core transform (W pre-split; x mask-split). 64 nodes/block.
// out96[n][j] = sum_d x[n][d]*Wall[d][j]  (j<64: basis; j>=64: loop)
// Epilogue: per-node scale s[n]; xbq packed int16 pair; agg init = loop + bias
// ---------------------------------------------------------------------------
template <int DIN>
__global__ __launch_bounds__(256, 3)
void transform_mma(const float* __restrict__ xin,
                   const float2* __restrict__ wsp,    // [DIN][96] pre-split
                   const float* __restrict__ bias,
                   unsigned* __restrict__ xbq,
                   float* __restrict__ sarr,
                   float* __restrict__ agg,
                   int nnodes)
{
    extern __shared__ char smraw[];
    float2* xs = (float2*)smraw;                 // [64][XS_STRIDE] {hi,lo}
    float2* ws = (float2*)(smraw + XS_BYTES);    // [32][WS_STRIDE]  {hi,lo}
    float*  outs = (float*)smraw;                // reused after compute

    const int tid = threadIdx.x;
    const int lane = tid & 31, wid = tid >> 5;
    const int warpM = wid & 1, warpN = wid >> 1;     // 2m x 4n
    const int gid = lane >> 2, tig = lane & 3;
    const int base = blockIdx.x * MROWS;

    float c[2][3][4];
#pragma unroll
    for (int mt = 0; mt < 2; mt++)
#pragma unroll
        for (int nt = 0; nt < 3; nt++)
#pragma unroll
            for (int q = 0; q < 4; q++) c[mt][nt][q] = 0.f;

    const int NCHUNK = DIN / 32;
#pragma unroll 1
    for (int ch = 0; ch < NCHUNK; ch++) {
        const int kbase = ch * 32;
        if (ch) __syncthreads();
        // stage x chunk: 64 rows x 32 cols via float4 + mask split
        for (int idx = tid; idx < MROWS * 8; idx += 256) {
            int row = idx >> 3, c4 = (idx & 7) * 4;
            int node = base + row;
            float4 v = (node < nnodes)
                ? *(const float4*)(xin + (long)node * DIN + kbase + c4)
                : make_float4(0.f, 0.f, 0.f, 0.f);
            float2 p0 = msplit(v.x), p1 = msplit(v.y);
            float2 p2 = msplit(v.z), p3 = msplit(v.w);
            float4* dst = (float4*)&xs[row * XS_STRIDE + c4];
            dst[0] = make_float4(p0.x, p0.y, p1.x, p1.y);
            dst[1] = make_float4(p2.x, p2.y, p3.x, p3.y);
        }
        // stage W chunk (pre-split): 32 x 96 float2, via float4 copies
        for (int idx = tid; idx < 32 * 48; idx += 256) {
            int k = idx / 48, j2 = (idx % 48) * 2;
            float4 v = *(const float4*)&wsp[(kbase + k) * 96 + j2];
            *(float4*)&ws[k * WS_STRIDE + j2] = v;
        }
        __syncthreads();

#pragma unroll
        for (int ks = 0; ks < 32; ks += 8) {
            unsigned ahi[2][4], alo[2][4];
#pragma unroll
            for (int mt = 0; mt < 2; mt++) {
                int r0 = warpM * 32 + mt * 16 + gid;
                float2 a0 = xs[(r0    ) * XS_STRIDE + ks + tig];
                float2 a1 = xs[(r0 + 8) * XS_STRIDE + ks + tig];
                float2 a2 = xs[(r0    ) * XS_STRIDE + ks + tig + 4];
                float2 a3 = xs[(r0 + 8) * XS_STRIDE + ks + tig + 4];
                ahi[mt][0] = __float_as_uint(a0.x); alo[mt][0] = __float_as_uint(a0.y);
                ahi[mt][1] = __float_as_uint(a1.x); alo[mt][1] = __float_as_uint(a1.y);
                ahi[mt][2] = __float_as_uint(a2.x); alo[mt][2] = __float_as_uint(a2.y);
                ahi[mt][3] = __float_as_uint(a3.x); alo[mt][3] = __float_as_uint(a3.y);
            }
            unsigned bhi[3][2], blo[3][2];
#pragma unroll
            for (int nt = 0; nt < 3; nt++) {
                int n = warpN * 24 + nt * 8 + gid;
                float2 b0 = ws[(ks + tig    ) * WS_STRIDE + n];
                float2 b1 = ws[(ks + tig + 4) * WS_STRIDE + n];
                bhi[nt][0] = __float_as_uint(b0.x); blo[nt][0] = __float_as_uint(b0.y);
                bhi[nt][1] = __float_as_uint(b1.x); blo[nt][1] = __float_as_uint(b1.y);
            }
#pragma unroll
            for (int mt = 0; mt < 2; mt++)
#pragma unroll
                for (int nt = 0; nt < 3; nt++) {
                    mma8(c[mt][nt], ahi[mt], bhi[nt]);
                    mma8(c[mt][nt], ahi[mt], blo[nt]);
                    mma8(c[mt][nt], alo[mt], bhi[nt]);
                }
        }
    }
    __syncthreads();   // compute smem dead; reuse as outs

#pragma unroll
    for (int mt = 0; mt < 2; mt++)
#pragma unroll
        for (int nt = 0; nt < 3; nt++) {
            int r0 = warpM * 32 + mt * 16 + gid;
            int c0 = warpN * 24 + nt * 8 + tig * 2;
            outs[(r0    ) * OS_STRIDE + c0    ] = c[mt][nt][0];
            outs[(r0    ) * OS_STRIDE + c0 + 1] = c[mt][nt][1];
            outs[(r0 + 8) * OS_STRIDE + c0    ] = c[mt][nt][2];
            outs[(r0 + 8) * OS_STRIDE + c0 + 1] = c[mt][nt][3];
        }
    __syncthreads();

    // Epilogue: per-node max -> scale; quantize basis pair; agg init.
    for (int idx = tid; idx < MROWS * 32; idx += 256) {
        int row = idx >> 5, o = idx & 31;
        int node = base + row;
        float v0 = outs[row * OS_STRIDE + o];
        float v1 = outs[row * OS_STRIDE + 32 + o];
        float m = fmaxf(fabsf(v0), fabsf(v1));
#pragma unroll
        for (int off = 16; off; off >>= 1)
            m = fmaxf(m, __shfl_xor_sync(0xFFFFFFFFu, m, off));
        float k = (m > 1e-20f) ? 32767.0f / m : 0.f;
        int q0 = __float2int_rn(v0 * k);
        int q1 = __float2int_rn(v1 * k);
        unsigned pk = ((unsigned)q0 & 0xFFFFu) | ((unsigned)q1 << 16);
        if (node < nnodes) {
            xbq[(long)node * 32 + o] = pk;
            if (o == 0) sarr[node] = (m > 1e-20f) ? m * (1.0f / 32767.0f) : 0.f;
            agg[(long)node * 32 + o] = outs[row * OS_STRIDE + 64 + o] + bias[o];
        }
    }
}

// ------------------------ CSR build ---------------------------------------
__global__ void k_zero(int* p, int n)
{
    int i = blockIdx.x * blockDim.x + threadIdx.x;
    if (i < n) p[i] = 0;
}
__global__ void k_hist(const int* __restrict__ dst, int* __restrict__ deg, int ne)
{
    int i = blockIdx.x * blockDim.x + threadIdx.x;
    if (i < ne) atomicAdd(&deg[dst[i]], 1);
}
__global__ void k_blocksum(const int* __restrict__ deg, int* __restrict__ bsum, int n)
{
    __shared__ int wsum[32];
    int i = blockIdx.x * SCAN_BS + threadIdx.x;
    int v = (i < n) ? deg[i] : 0;
#pragma unroll
    for (int o = 16; o; o >>= 1) v += __shfl_down_sync(0xFFFFFFFFu, v, o);
    int lane = threadIdx.x & 31, wid = threadIdx.x >> 5;
    if (lane == 0) wsum[wid] = v;
    __syncthreads();
    if (wid == 0) {
        int x = wsum[lane];
#pragma unroll
        for (int o = 16; o; o >>= 1) x += __shfl_down_sync(0xFFFFFFFFu, x, o);
        if (lane == 0) bsum[blockIdx.x] = x;
    }
}
__global__ void k_scantop(int* __restrict__ bsum, int nb, int* __restrict__ rowptr_end)
{
    __shared__ int s[128];
    int t = threadIdx.x;
    int v = (t < nb) ? bsum[t] : 0;
    s[t] = v;
    __syncthreads();
#pragma unroll
    for (int o = 1; o < 128; o <<= 1) {
        int y = (t >= o) ? s[t - o] : 0;
        __syncthreads();
        s[t] += y;
        __syncthreads();
    }
    if (t < nb) bsum[t] = s[t] - v;
    if (t == 127) *rowptr_end = s[127];
}
__global__ void k_scanapply(const int* __restrict__ deg, const int* __restrict__ bsum,
                            int* __restrict__ rowptr, int* __restrict__ cursor, int n)
{
    __shared__ int wsum[32];
    int i = blockIdx.x * SCAN_BS + threadIdx.x;
    int v = (i < n) ? deg[i] : 0;
    int lane = threadIdx.x & 31, wid = threadIdx.x >> 5;
    unsigned fm = 0xFFFFFFFFu;
    int x = v;
#pragma unroll
    for (int o = 1; o < 32; o <<= 1) {
        int y = __shfl_up_sync(fm, x, o);
        if (lane >= o) x += y;
    }
    if (lane == 31) wsum[wid] = x;
    __syncthreads();
    if (wid == 0) {
        int w = wsum[lane];
        int wx = w;
#pragma unroll
        for (int o = 1; o < 32; o <<= 1) {
            int y = __shfl_up_sync(fm, wx, o);
            if (lane >= o) wx += y;
        }
        wsum[lane] = wx - w;
    }
    __syncthreads();
    int excl = (x - v) + wsum[wid] + bsum[blockIdx.x];
    if (i < n) { rowptr[i] = excl; cursor[i] = excl; }
}
__global__ void k_scatter(const int* __restrict__ src, const int* __restrict__ dst,
                          const int* __restrict__ etype, const float* __restrict__ mask,
                          int* __restrict__ cursor, int2* __restrict__ meta, int ne)
{
    int e = blockIdx.x * blockDim.x + threadIdx.x;
    if (e >= ne) return;
    int d = dst[e];
    int pos = atomicAdd(&cursor[d], 1);
    meta[pos] = make_int2(src[e] | (etype[e] << 17), __float_as_int(mask[e]));
}

// ---------------------------------------------------------------------------
// Aggregate: warp per node. Per edge: uniform meta + uniform s[src] broadcast
// gather + ONE 128B int16-pair gather. Fused tanh.
// ---------------------------------------------------------------------------
__global__ void k_aggregate(const unsigned* __restrict__ xbq,
                            const float* __restrict__ sarr,
                            const float* __restrict__ agginit,
                            const int* __restrict__ rowptr,
                            const int2* __restrict__ meta,
                            const float* __restrict__ comp,  // [5][2]
                            float* __restrict__ h, int nn)
{
    __shared__ float cl[16];
    if (threadIdx.x < 10) cl[threadIdx.x] = comp[threadIdx.x];
    __syncthreads();
    const int lane = threadIdx.x & 31;
    const int w = (blockIdx.x * blockDim.x + threadIdx.x) >> 5;
    if (w >= nn) return;
    float acc = agginit[(long)w * 32 + lane];
    int i = rowptr[w];
    const int end = rowptr[w + 1];
    for (; i + 4 <= end; i += 4) {
        int2 m0 = __ldg(&meta[i]);
        int2 m1 = __ldg(&meta[i + 1]);
        int2 m2 = __ldg(&meta[i + 2]);
        int2 m3 = __ldg(&meta[i + 3]);
        int s0 = m0.x & 0x1FFFF, s1 = m1.x & 0x1FFFF;
        int s2 = m2.x & 0x1FFFF, s3 = m3.x & 0x1FFFF;
        float t0 = __int_as_float(m0.y) * __ldg(&sarr[s0]);
        float t1 = __int_as_float(m1.y) * __ldg(&sarr[s1]);
        float t2 = __int_as_float(m2.y) * __ldg(&sarr[s2]);
        float t3 = __int_as_float(m3.y) * __ldg(&sarr[s3]);
        unsigned u0 = __ldg(&xbq[(long)s0 * 32 + lane]);
        unsigned u1 = __ldg(&xbq[(long)s1 * 32 + lane]);
        unsigned u2 = __ldg(&xbq[(long)s2 * 32 + lane]);
        unsigned u3 = __ldg(&xbq[(long)s3 * 32 + lane]);
        int r0 = (m0.x >> 17) * 2, r1 = (m1.x >> 17) * 2;
        int r2 = (m2.x >> 17) * 2, r3 = (m3.x >> 17) * 2;
        float a0 = (float)((int)(u0 << 16) >> 16), b0 = (float)((int)u0 >> 16);
        float a1 = (float)((int)(u1 << 16) >> 16), b1 = (float)((int)u1 >> 16);
        float a2 = (float)((int)(u2 << 16) >> 16), b2 = (float)((int)u2 >> 16);
        float a3 = (float)((int)(u3 << 16) >> 16), b3 = (float)((int)u3 >> 16);
        acc = fmaf(t0, fmaf(cl[r0], a0, cl[r0 + 1] * b0), acc);
        acc = fmaf(t1, fmaf(cl[r1], a1, cl[r1 + 1] * b1), acc);
        acc = fmaf(t2, fmaf(cl[r2], a2, cl[r2 + 1] * b2), acc);
        acc = fmaf(t3, fmaf(cl[r3], a3, cl[r3 + 1] * b3), acc);
    }
    for (; i < end; i++) {
        int2 md = __ldg(&meta[i]);
        int sidx = md.x & 0x1FFFF;
        float tv = __int_as_float(md.y) * __ldg(&sarr[sidx]);
        unsigned u = __ldg(&xbq[(long)sidx * 32 + lane]);
        int r = (md.x >> 17) * 2;
        float a = (float)((int)(u << 16) >> 16), b = (float)((int)u >> 16);
        acc = fmaf(tv, fmaf(cl[r], a, cl[r + 1] * b), acc);
    }
    h[(long)w * 32 + lane] = tanhf(acc);
}

// ---------------------------------------------------------------------------
#define PPB 32
__global__ void head_kernel(const float* __restrict__ h1,
                            const float* __restrict__ h2,
                            const float* __restrict__ h3,
                            const int* __restrict__ users,
                            const int* __restrict__ items,
                            const float* __restrict__ w1,
                            const float* __restrict__ bw1,
                            const float* __restrict__ w2,
                            const float* __restrict__ bw2,
                            float* __restrict__ out,
                            int npairs)
{
    extern __shared__ float sm[];
    float* w1s = sm;
    float* feats = sm + 24576;
    const int tid = threadIdx.x;

    for (int idx = tid; idx < 24576; idx += 128) w1s[idx] = w1[idx];
    const float bb = bw1[tid];
    const float wv2 = w2[tid];
    const float b2v = bw2[0];
    __shared__ float red[4];
    __syncthreads();

    const int pend = min((blockIdx.x + 1) * PPB, npairs);
    for (int p = blockIdx.x * PPB; p < pend; p++) {
        if (tid < 96) {
            int u = __ldg(&users[p]);
            int it = __ldg(&items[p]);
            int o = tid & 31;
            const float* hu = (tid < 32) ? h1 : (tid < 64) ? h2 : h3;
            feats[tid] = hu[(long)u * 32 + o];
            feats[96 + tid] = hu[(long)it * 32 + o];
        }
        __syncthreads();
        float acc = bb;
#pragma unroll 16
        for (int k = 0; k < 192; k++)
            acc = fmaf(feats[k], w1s[k * 128 + tid], acc);
        float hv = fmaxf(acc, 0.f) * wv2;
#pragma unroll
        for (int off = 16; off; off >>= 1) hv += __shfl_down_sync(0xFFFFFFFFu, hv, off);
        if ((tid & 31) == 0) red[tid >> 5] = hv;
        __syncthreads();
        if (tid == 0) out[p] = red[0] + red[1] + red[2] + red[3] + b2v;
        __syncthreads();
    }
}

// ---------------------------------------------------------------------------
extern "C" void kernel_launch(void* const* d_in, const int* in_sizes, int n_in,
                              void* d_out, int out_size)
{
    const float* x     = (const float*)d_in[0];
    const float* emask = (const float*)d_in[1];
    const int*   etype = (const int*)d_in[2];
    const int*   src   = (const int*)d_in[3];
    const int*   dst   = (const int*)d_in[4];
    const int*   users = (const int*)d_in[5];
    const int*   items = (const int*)d_in[6];
    const float* V1    = (const float*)d_in[7];
    const float* comp1 = (const float*)d_in[8];
    const float* loop1 = (const float*)d_in[9];
    const float* b1    = (const float*)d_in[10];
    const float* V2    = (const float*)d_in[11];
    const float* comp2 = (const float*)d_in[12];
    const float* loop2 = (const float*)d_in[13];
    const float* b2    = (const float*)d_in[14];
    const float* V3    = (const float*)d_in[15];
    const float* comp3 = (const float*)d_in[16];
    const float* loop3 = (const float*)d_in[17];
    const float* b3    = (const float*)d_in[18];
    const float* w1    = (const float*)d_in[19];
    const float* bw1   = (const float*)d_in[20];
    const float* w2    = (const float*)d_in[21];
    const float* bw2   = (const float*)d_in[22];
    float* out = (float*)d_out;

    unsigned* xbq;
    float *sarr, *agg, *h1, *h2, *h3;
    float2 *wsp1, *wsp2, *wsp3;
    int *deg, *bsum, *rowptr, *cursor;
    int2* meta;
    cudaGetSymbolAddress((void**)&xbq,    g_xbq);
    cudaGetSymbolAddress((void**)&sarr,   g_s);
    cudaGetSymbolAddress((void**)&agg,    g_agg);
    cudaGetSymbolAddress((void**)&h1,     g_h1);
    cudaGetSymbolAddress((void**)&h2,     g_h2);
    cudaGetSymbolAddress((void**)&h3,     g_h3);
    cudaGetSymbolAddress((void**)&deg,    g_deg);
    cudaGetSymbolAddress((void**)&bsum,   g_bsum);
    cudaGetSymbolAddress((void**)&rowptr, g_rowptr);
    cudaGetSymbolAddress((void**)&cursor, g_cursor);
    cudaGetSymbolAddress((void**)&meta,   g_meta);
    cudaGetSymbolAddress((void**)&wsp1,   g_wsp1);
    cudaGetSymbolAddress((void**)&wsp2,   g_wsp2);
    cudaGetSymbolAddress((void**)&wsp3,   g_wsp3);

    const int smem_hd = (24576 + 192) * 4;
    cudaFuncSetAttribute(transform_mma<INF>, cudaFuncAttributeMaxDynamicSharedMemorySize, TSMEM);
    cudaFuncSetAttribute(transform_mma<HID>, cudaFuncAttributeMaxDynamicSharedMemorySize, TSMEM);
    cudaFuncSetAttribute(head_kernel, cudaFuncAttributeMaxDynamicSharedMemorySize, smem_hd);

    const int tgrid = (NN + MROWS - 1) / MROWS;   // 1563
    const int agrid = (NN * 32 + 255) / 256;      // 12500
    const int egrid = (NE + 255) / 256;

    // Prep + CSR build; transform<128> at launch index 3 for ncu.
    k_zero<<<(NN + 255) / 256, 256>>>(deg, NN);
    k_hist<<<egrid, 256>>>(dst, deg, NE);
    k_wsplit<<<(INF * 96 + 255) / 256, 256>>>(V1, loop1, wsp1, INF);
    transform_mma<INF><<<tgrid, 256, TSMEM>>>(x, wsp1, b1, xbq, sarr, agg, NN);
    k_wsplit<<<(HID * 96 + 255) / 256, 256>>>(V2, loop2, wsp2, HID);
    k_wsplit<<<(HID * 96 + 255) / 256, 256>>>(V3, loop3, wsp3, HID);
    k_blocksum<<<NB, SCAN_BS>>>(deg, bsum, NN);
    k_scantop<<<1, 128>>>(bsum, NB, rowptr + NN);
    k_scanapply<<<NB, SCAN_BS>>>(deg, bsum, rowptr, cursor, NN);
    k_scatter<<<egrid, 256>>>(src, dst, etype, emask, cursor, meta, NE);

    // Layer 1
    k_aggregate<<<agrid, 256>>>(xbq, sarr, agg, rowptr, meta, comp1, h1, NN);
    // Layer 2
    transform_mma<HID><<<tgrid, 256, TSMEM>>>(h1, wsp2, b2, xbq, sarr, agg, NN);
    k_aggregate<<<agrid, 256>>>(xbq, sarr, agg, rowptr, meta, comp2, h2, NN);
    // Layer 3
    transform_mma<HID><<<tgrid, 256, TSMEM>>>(h2, wsp3, b3, xbq, sarr, agg, NN);
    k_aggregate<<<agrid, 256>>>(xbq, sarr, agg, rowptr, meta, comp3, h3, NN);
    // Head
    head_kernel<<<(NPAIRS + PPB - 1) / PPB, 128, smem_hd>>>(
        h1, h2, h3, users, items, w1, bw1, w2, bw2, out, NPAIRS);
}

// round 9
// speedup vs baseline: 1.3741x; 1.0557x over previous
#include <cuda_runtime.h>
#include <math.h>

#define NN 100000
#define NE 1600000
#define INF 128
#define HID 32
#define NPAIRS 4096
#define SCAN_BS 1024
#define NB ((NN + SCAN_BS - 1) / SCAN_BS)   // 98

// scratch (device globals)
__device__ unsigned g_xbq[NN * 32];    // packed int16 pair {q0,q1} per (node,o) — 12.8MB
__device__ float    g_s[NN];           // per-node decode scale
__device__ float    g_agg[NN * 32];    // agg init (loop term + bias)
__device__ float    g_h1[NN * 32];
__device__ float    g_h2[NN * 32];
__device__ float    g_h3[NN * 32];
__device__ int      g_deg[NN];
__device__ int      g_bsum[NB + 1];
__device__ int      g_rowptr[NN + 1];
__device__ int      g_cursor[NN];
__device__ int2     g_meta[NE];        // {src | etype<<17, mask_bits} grouped by dst
__device__ float2   g_wsp1[INF * 96];  // pre-split tf32 {hi,lo} weights
__device__ float2   g_wsp2[HID * 96];
__device__ float2   g_wsp3[HID * 96];

// ---------------------------------------------------------------------------
#define MROWS 64
#define XS_STRIDE 36
#define WS_STRIDE 100
#define OS_STRIDE 104
#define XS_BYTES  (MROWS * XS_STRIDE * 8)         // 18432
#define WS_BYTES  (32 * WS_STRIDE * 8)            // 25600
#define TSMEM     (XS_BYTES + WS_BYTES)           // 44032

__device__ __forceinline__ void mma8(float* c, const unsigned* a, const unsigned* b) {
    asm volatile("mma.sync.aligned.m16n8k8.row.col.f32.tf32.tf32.f32 "
                 "{%0,%1,%2,%3}, {%4,%5,%6,%7}, {%8,%9}, {%0,%1,%2,%3};"
                 : "+f"(c[0]), "+f"(c[1]), "+f"(c[2]), "+f"(c[3])
                 : "r"(a[0]), "r"(a[1]), "r"(a[2]), "r"(a[3]), "r"(b[0]), "r"(b[1]));
}
__device__ __forceinline__ float2 msplit(float v) {
    float hi = __uint_as_float(__float_as_uint(v) & 0xFFFFE000u);
    return make_float2(hi, v - hi);
}

__global__ void k_wsplit(const float* __restrict__ V, const float* __restrict__ loopw,
                         float2* __restrict__ wsp, int DIN)
{
    int idx = blockIdx.x * blockDim.x + threadIdx.x;
    if (idx >= DIN * 96) return;
    int d = idx / 96, j = idx - d * 96;
    float w = (j < 64) ? V[(j >> 5) * DIN * 32 + d * 32 + (j & 31)]
                       : loopw[d * 32 + (j - 64)];
    wsp[idx] = msplit(w);
}

// ---------------------------------------------------------------------------
// Split-TF32 tensor-core transform (W pre-split; x mask-split). 64 nodes/block.
// ---------------------------------------------------------------------------
template <int DIN>
__global__ __launch_bounds__(256, 3)
void transform_mma(const float* __restrict__ xin,
                   const float2* __restrict__ wsp,
                   const float* __restrict__ bias,
                   unsigned* __restrict__ xbq,
                   float* __restrict__ sarr,
                   float* __restrict__ agg,
                   int nnodes)
{
    extern __shared__ char smraw[];
    float2* xs = (float2*)smraw;
    float2* ws = (float2*)(smraw + XS_BYTES);
    float*  outs = (float*)smraw;

    const int tid = threadIdx.x;
    const int lane = tid & 31, wid = tid >> 5;
    const int warpM = wid & 1, warpN = wid >> 1;
    const int gid = lane >> 2, tig = lane & 3;
    const int base = blockIdx.x * MROWS;

    float c[2][3][4];
#pragma unroll
    for (int mt = 0; mt < 2; mt++)
#pragma unroll
        for (int nt = 0; nt < 3; nt++)
#pragma unroll
            for (int q = 0; q < 4; q++) c[mt][nt][q] = 0.f;

    const int NCHUNK = DIN / 32;
#pragma unroll 1
    for (int ch = 0; ch < NCHUNK; ch++) {
        const int kbase = ch * 32;
        if (ch) __syncthreads();
        for (int idx = tid; idx < MROWS * 8; idx += 256) {
            int row = idx >> 3, c4 = (idx & 7) * 4;
            int node = base + row;
            float4 v = (node < nnodes)
                ? *(const float4*)(xin + (long)node * DIN + kbase + c4)
                : make_float4(0.f, 0.f, 0.f, 0.f);
            float2 p0 = msplit(v.x), p1 = msplit(v.y);
            float2 p2 = msplit(v.z), p3 = msplit(v.w);
            float4* dst = (float4*)&xs[row * XS_STRIDE + c4];
            dst[0] = make_float4(p0.x, p0.y, p1.x, p1.y);
            dst[1] = make_float4(p2.x, p2.y, p3.x, p3.y);
        }
        for (int idx = tid; idx < 32 * 48; idx += 256) {
            int k = idx / 48, j2 = (idx % 48) * 2;
            float4 v = *(const float4*)&wsp[(kbase + k) * 96 + j2];
            *(float4*)&ws[k * WS_STRIDE + j2] = v;
        }
        __syncthreads();

#pragma unroll
        for (int ks = 0; ks < 32; ks += 8) {
            unsigned ahi[2][4], alo[2][4];
#pragma unroll
            for (int mt = 0; mt < 2; mt++) {
                int r0 = warpM * 32 + mt * 16 + gid;
                float2 a0 = xs[(r0    ) * XS_STRIDE + ks + tig];
                float2 a1 = xs[(r0 + 8) * XS_STRIDE + ks + tig];
                float2 a2 = xs[(r0    ) * XS_STRIDE + ks + tig + 4];
                float2 a3 = xs[(r0 + 8) * XS_STRIDE + ks + tig + 4];
                ahi[mt][0] = __float_as_uint(a0.x); alo[mt][0] = __float_as_uint(a0.y);
                ahi[mt][1] = __float_as_uint(a1.x); alo[mt][1] = __float_as_uint(a1.y);
                ahi[mt][2] = __float_as_uint(a2.x); alo[mt][2] = __float_as_uint(a2.y);
                ahi[mt][3] = __float_as_uint(a3.x); alo[mt][3] = __float_as_uint(a3.y);
            }
            unsigned bhi[3][2], blo[3][2];
#pragma unroll
            for (int nt = 0; nt < 3; nt++) {
                int n = warpN * 24 + nt * 8 + gid;
                float2 b0 = ws[(ks + tig    ) * WS_STRIDE + n];
                float2 b1 = ws[(ks + tig + 4) * WS_STRIDE + n];
                bhi[nt][0] = __float_as_uint(b0.x); blo[nt][0] = __float_as_uint(b0.y);
                bhi[nt][1] = __float_as_uint(b1.x); blo[nt][1] = __float_as_uint(b1.y);
            }
#pragma unroll
            for (int mt = 0; mt < 2; mt++)
#pragma unroll
                for (int nt = 0; nt < 3; nt++) {
                    mma8(c[mt][nt], ahi[mt], bhi[nt]);
                    mma8(c[mt][nt], ahi[mt], blo[nt]);
                    mma8(c[mt][nt], alo[mt], bhi[nt]);
                }
        }
    }
    __syncthreads();

#pragma unroll
    for (int mt = 0; mt < 2; mt++)
#pragma unroll
        for (int nt = 0; nt < 3; nt++) {
            int r0 = warpM * 32 + mt * 16 + gid;
            int c0 = warpN * 24 + nt * 8 + tig * 2;
            outs[(r0    ) * OS_STRIDE + c0    ] = c[mt][nt][0];
            outs[(r0    ) * OS_STRIDE + c0 + 1] = c[mt][nt][1];
            outs[(r0 + 8) * OS_STRIDE + c0    ] = c[mt][nt][2];
            outs[(r0 + 8) * OS_STRIDE + c0 + 1] = c[mt][nt][3];
        }
    __syncthreads();

    for (int idx = tid; idx < MROWS * 32; idx += 256) {
        int row = idx >> 5, o = idx & 31;
        int node = base + row;
        float v0 = outs[row * OS_STRIDE + o];
        float v1 = outs[row * OS_STRIDE + 32 + o];
        float m = fmaxf(fabsf(v0), fabsf(v1));
#pragma unroll
        for (int off = 16; off; off >>= 1)
            m = fmaxf(m, __shfl_xor_sync(0xFFFFFFFFu, m, off));
        float k = (m > 1e-20f) ? 32767.0f / m : 0.f;
        int q0 = __float2int_rn(v0 * k);
        int q1 = __float2int_rn(v1 * k);
        unsigned pk = ((unsigned)q0 & 0xFFFFu) | ((unsigned)q1 << 16);
        if (node < nnodes) {
            xbq[(long)node * 32 + o] = pk;
            if (o == 0) sarr[node] = (m > 1e-20f) ? m * (1.0f / 32767.0f) : 0.f;
            agg[(long)node * 32 + o] = outs[row * OS_STRIDE + 64 + o] + bias[o];
        }
    }
}

// ------------------------ CSR build ---------------------------------------
__global__ void k_zero(int* p, int n)
{
    int i = blockIdx.x * blockDim.x + threadIdx.x;
    if (i < n) p[i] = 0;
}
__global__ void k_hist(const int* __restrict__ dst, int* __restrict__ deg, int ne)
{
    int i = blockIdx.x * blockDim.x + threadIdx.x;
    if (i < ne) atomicAdd(&deg[dst[i]], 1);
}
__global__ void k_blocksum(const int* __restrict__ deg, int* __restrict__ bsum, int n)
{
    __shared__ int wsum[32];
    int i = blockIdx.x * SCAN_BS + threadIdx.x;
    int v = (i < n) ? deg[i] : 0;
#pragma unroll
    for (int o = 16; o; o >>= 1) v += __shfl_down_sync(0xFFFFFFFFu, v, o);
    int lane = threadIdx.x & 31, wid = threadIdx.x >> 5;
    if (lane == 0) wsum[wid] = v;
    __syncthreads();
    if (wid == 0) {
        int x = wsum[lane];
#pragma unroll
        for (int o = 16; o; o >>= 1) x += __shfl_down_sync(0xFFFFFFFFu, x, o);
        if (lane == 0) bsum[blockIdx.x] = x;
    }
}
__global__ void k_scantop(int* __restrict__ bsum, int nb, int* __restrict__ rowptr_end)
{
    __shared__ int s[128];
    int t = threadIdx.x;
    int v = (t < nb) ? bsum[t] : 0;
    s[t] = v;
    __syncthreads();
#pragma unroll
    for (int o = 1; o < 128; o <<= 1) {
        int y = (t >= o) ? s[t - o] : 0;
        __syncthreads();
        s[t] += y;
        __syncthreads();
    }
    if (t < nb) bsum[t] = s[t] - v;
    if (t == 127) *rowptr_end = s[127];
}
__global__ void k_scanapply(const int* __restrict__ deg, const int* __restrict__ bsum,
                            int* __restrict__ rowptr, int* __restrict__ cursor, int n)
{
    __shared__ int wsum[32];
    int i = blockIdx.x * SCAN_BS + threadIdx.x;
    int v = (i < n) ? deg[i] : 0;
    int lane = threadIdx.x & 31, wid = threadIdx.x >> 5;
    unsigned fm = 0xFFFFFFFFu;
    int x = v;
#pragma unroll
    for (int o = 1; o < 32; o <<= 1) {
        int y = __shfl_up_sync(fm, x, o);
        if (lane >= o) x += y;
    }
    if (lane == 31) wsum[wid] = x;
    __syncthreads();
    if (wid == 0) {
        int w = wsum[lane];
        int wx = w;
#pragma unroll
        for (int o = 1; o < 32; o <<= 1) {
            int y = __shfl_up_sync(fm, wx, o);
            if (lane >= o) wx += y;
        }
        wsum[lane] = wx - w;
    }
    __syncthreads();
    int excl = (x - v) + wsum[wid] + bsum[blockIdx.x];
    if (i < n) { rowptr[i] = excl; cursor[i] = excl; }
}
__global__ void k_scatter(const int* __restrict__ src, const int* __restrict__ dst,
                          const int* __restrict__ etype, const float* __restrict__ mask,
                          int* __restrict__ cursor, int2* __restrict__ meta, int ne)
{
    int e = blockIdx.x * blockDim.x + threadIdx.x;
    if (e >= ne) return;
    int d = dst[e];
    int pos = atomicAdd(&cursor[d], 1);
    meta[pos] = make_int2(src[e] | (etype[e] << 17), __float_as_int(mask[e]));
}

// ---------------------------------------------------------------------------
// Aggregate: warp per node, 8-deep load batching for MLP.
// ---------------------------------------------------------------------------
__global__ void k_aggregate(const unsigned* __restrict__ xbq,
                            const float* __restrict__ sarr,
                            const float* __restrict__ agginit,
                            const int* __restrict__ rowptr,
                            const int2* __restrict__ meta,
                            const float* __restrict__ comp,
                            float* __restrict__ h, int nn)
{
    __shared__ float cl[16];
    if (threadIdx.x < 10) cl[threadIdx.x] = comp[threadIdx.x];
    __syncthreads();
    const int lane = threadIdx.x & 31;
    const int w = (blockIdx.x * blockDim.x + threadIdx.x) >> 5;
    if (w >= nn) return;
    float acc = agginit[(long)w * 32 + lane];
    int i = rowptr[w];
    const int end = rowptr[w + 1];
    for (; i + 8 <= end; i += 8) {
        int2 mm[8];
#pragma unroll
        for (int j = 0; j < 8; j++) mm[j] = __ldg(&meta[i + j]);
        unsigned uu[8];
#pragma unroll
        for (int j = 0; j < 8; j++)
            uu[j] = __ldg(&xbq[(long)(mm[j].x & 0x1FFFF) * 32 + lane]);
        float tv[8];
#pragma unroll
        for (int j = 0; j < 8; j++)
            tv[j] = __int_as_float(mm[j].y) * __ldg(&sarr[mm[j].x & 0x1FFFF]);
#pragma unroll
        for (int j = 0; j < 8; j++) {
            int r = (mm[j].x >> 17) * 2;
            float a = (float)((int)(uu[j] << 16) >> 16);
            float b = (float)((int)uu[j] >> 16);
            acc = fmaf(tv[j], fmaf(cl[r], a, cl[r + 1] * b), acc);
        }
    }
    for (; i + 4 <= end; i += 4) {
        int2 mm[4];
#pragma unroll
        for (int j = 0; j < 4; j++) mm[j] = __ldg(&meta[i + j]);
        unsigned uu[4];
#pragma unroll
        for (int j = 0; j < 4; j++)
            uu[j] = __ldg(&xbq[(long)(mm[j].x & 0x1FFFF) * 32 + lane]);
#pragma unroll
        for (int j = 0; j < 4; j++) {
            float tvj = __int_as_float(mm[j].y) * __ldg(&sarr[mm[j].x & 0x1FFFF]);
            int r = (mm[j].x >> 17) * 2;
            float a = (float)((int)(uu[j] << 16) >> 16);
            float b = (float)((int)uu[j] >> 16);
            acc = fmaf(tvj, fmaf(cl[r], a, cl[r + 1] * b), acc);
        }
    }
    for (; i < end; i++) {
        int2 md = __ldg(&meta[i]);
        int sidx = md.x & 0x1FFFF;
        float tv = __int_as_float(md.y) * __ldg(&sarr[sidx]);
        unsigned u = __ldg(&xbq[(long)sidx * 32 + lane]);
        int r = (md.x >> 17) * 2;
        float a = (float)((int)(u << 16) >> 16), b = (float)((int)u >> 16);
        acc = fmaf(tv, fmaf(cl[r], a, cl[r + 1] * b), acc);
    }
    h[(long)w * 32 + lane] = tanhf(acc);
}

// ---------------------------------------------------------------------------
#define PPB 32
__global__ void head_kernel(const float* __restrict__ h1,
                            const float* __restrict__ h2,
                            const float* __restrict__ h3,
                            const int* __restrict__ users,
                            const int* __restrict__ items,
                            const float* __restrict__ w1,
                            const float* __restrict__ bw1,
                            const float* __restrict__ w2,
                            const float* __restrict__ bw2,
                            float* __restrict__ out,
                            int npairs)
{
    extern __shared__ float sm[];
    float* w1s = sm;
    float* feats = sm + 24576;
    const int tid = threadIdx.x;

    for (int idx = tid; idx < 24576; idx += 128) w1s[idx] = w1[idx];
    const float bb = bw1[tid];
    const float wv2 = w2[tid];
    const float b2v = bw2[0];
    __shared__ float red[4];
    __syncthreads();

    const int pend = min((blockIdx.x + 1) * PPB, npairs);
    for (int p = blockIdx.x * PPB; p < pend; p++) {
        if (tid < 96) {
            int u = __ldg(&users[p]);
            int it = __ldg(&items[p]);
            int o = tid & 31;
            const float* hu = (tid < 32) ? h1 : (tid < 64) ? h2 : h3;
            feats[tid] = hu[(long)u * 32 + o];
            feats[96 + tid] = hu[(long)it * 32 + o];
        }
        __syncthreads();
        float acc = bb;
#pragma unroll 16
        for (int k = 0; k < 192; k++)
            acc = fmaf(feats[k], w1s[k * 128 + tid], acc);
        float hv = fmaxf(acc, 0.f) * wv2;
#pragma unroll
        for (int off = 16; off; off >>= 1) hv += __shfl_down_sync(0xFFFFFFFFu, hv, off);
        if ((tid & 31) == 0) red[tid >> 5] = hv;
        __syncthreads();
        if (tid == 0) out[p] = red[0] + red[1] + red[2] + red[3] + b2v;
        __syncthreads();
    }
}

// ---------------------------------------------------------------------------
extern "C" void kernel_launch(void* const* d_in, const int* in_sizes, int n_in,
                              void* d_out, int out_size)
{
    const float* x     = (const float*)d_in[0];
    const float* emask = (const float*)d_in[1];
    const int*   etype = (const int*)d_in[2];
    const int*   src   = (const int*)d_in[3];
    const int*   dst   = (const int*)d_in[4];
    const int*   users = (const int*)d_in[5];
    const int*   items = (const int*)d_in[6];
    const float* V1    = (const float*)d_in[7];
    const float* comp1 = (const float*)d_in[8];
    const float* loop1 = (const float*)d_in[9];
    const float* b1    = (const float*)d_in[10];
    const float* V2    = (const float*)d_in[11];
    const float* comp2 = (const float*)d_in[12];
    const float* loop2 = (const float*)d_in[13];
    const float* b2    = (const float*)d_in[14];
    const float* V3    = (const float*)d_in[15];
    const float* comp3 = (const float*)d_in[16];
    const float* loop3 = (const float*)d_in[17];
    const float* b3    = (const float*)d_in[18];
    const float* w1    = (const float*)d_in[19];
    const float* bw1   = (const float*)d_in[20];
    const float* w2    = (const float*)d_in[21];
    const float* bw2   = (const float*)d_in[22];
    float* out = (float*)d_out;

    unsigned* xbq;
    float *sarr, *agg, *h1, *h2, *h3;
    float2 *wsp1, *wsp2, *wsp3;
    int *deg, *bsum, *rowptr, *cursor;
    int2* meta;
    cudaGetSymbolAddress((void**)&xbq,    g_xbq);
    cudaGetSymbolAddress((void**)&sarr,   g_s);
    cudaGetSymbolAddress((void**)&agg,    g_agg);
    cudaGetSymbolAddress((void**)&h1,     g_h1);
    cudaGetSymbolAddress((void**)&h2,     g_h2);
    cudaGetSymbolAddress((void**)&h3,     g_h3);
    cudaGetSymbolAddress((void**)&deg,    g_deg);
    cudaGetSymbolAddress((void**)&bsum,   g_bsum);
    cudaGetSymbolAddress((void**)&rowptr, g_rowptr);
    cudaGetSymbolAddress((void**)&cursor, g_cursor);
    cudaGetSymbolAddress((void**)&meta,   g_meta);
    cudaGetSymbolAddress((void**)&wsp1,   g_wsp1);
    cudaGetSymbolAddress((void**)&wsp2,   g_wsp2);
    cudaGetSymbolAddress((void**)&wsp3,   g_wsp3);

    const int smem_hd = (24576 + 192) * 4;
    cudaFuncSetAttribute(transform_mma<INF>, cudaFuncAttributeMaxDynamicSharedMemorySize, TSMEM);
    cudaFuncSetAttribute(transform_mma<HID>, cudaFuncAttributeMaxDynamicSharedMemorySize, TSMEM);
    cudaFuncSetAttribute(head_kernel, cudaFuncAttributeMaxDynamicSharedMemorySize, smem_hd);

    const int tgrid = (NN + MROWS - 1) / MROWS;   // 1563
    const int agrid = (NN * 32 + 255) / 256;      // 12500
    const int egrid = (NE + 255) / 256;

    // one-time side stream + events (created outside capture on first call;
    // graph replay uses only the dependency structure, not the handles)
    static cudaStream_t s2 = nullptr;
    static cudaEvent_t ev0 = nullptr, ev1 = nullptr;
    if (!s2) {
        cudaStreamCreateWithFlags(&s2, cudaStreamNonBlocking);
        cudaEventCreateWithFlags(&ev0, cudaEventDisableTiming);
        cudaEventCreateWithFlags(&ev1, cudaEventDisableTiming);
    }

    // fork: CSR build on s2 runs concurrently with wsplit + transform1
    cudaEventRecord(ev0, 0);
    cudaStreamWaitEvent(s2, ev0, 0);

    // main stream: weight prep + layer-1 transform (index-4 launch = profiled)
    k_wsplit<<<(INF * 96 + 255) / 256, 256>>>(V1, loop1, wsp1, INF);
    k_wsplit<<<(HID * 96 + 255) / 256, 256>>>(V2, loop2, wsp2, HID);
    k_wsplit<<<(HID * 96 + 255) / 256, 256>>>(V3, loop3, wsp3, HID);
    transform_mma<INF><<<tgrid, 256, TSMEM>>>(x, wsp1, b1, xbq, sarr, agg, NN);

    // side stream: CSR build
    k_zero<<<(NN + 255) / 256, 256, 0, s2>>>(deg, NN);
    k_hist<<<egrid, 256, 0, s2>>>(dst, deg, NE);
    k_blocksum<<<NB, SCAN_BS, 0, s2>>>(deg, bsum, NN);
    k_scantop<<<1, 128, 0, s2>>>(bsum, NB, rowptr + NN);
    k_scanapply<<<NB, SCAN_BS, 0, s2>>>(deg, bsum, rowptr, cursor, NN);
    k_scatter<<<egrid, 256, 0, s2>>>(src, dst, etype, emask, cursor, meta, NE);

    // join
    cudaEventRecord(ev1, s2);
    cudaStreamWaitEvent(0, ev1, 0);

    // Layer 1 aggregate
    k_aggregate<<<agrid, 256>>>(xbq, sarr, agg, rowptr, meta, comp1, h1, NN);
    // Layer 2
    transform_mma<HID><<<tgrid, 256, TSMEM>>>(h1, wsp2, b2, xbq, sarr, agg, NN);
    k_aggregate<<<agrid, 256>>>(xbq, sarr, agg, rowptr, meta, comp2, h2, NN);
    // Layer 3
    transform_mma<HID><<<tgrid, 256, TSMEM>>>(h2, wsp3, b3, xbq, sarr, agg, NN);
    k_aggregate<<<agrid, 256>>>(xbq, sarr, agg, rowptr, meta, comp3, h3, NN);
    // Head
    head_kernel<<<(NPAIRS + PPB - 1) / PPB, 128, smem_hd>>>(
        h1, h2, h3, users, items, w1, bw1, w2, bw2, out, NPAIRS);
}

// round 10
// speedup vs baseline: 1.4424x; 1.0497x over previous
#include <cuda_runtime.h>
#include <math.h>

#define NN 100000
#define NE 1600000
#define INF 128
#define HID 32
#define NPAIRS 4096
#define SCAN_BS 1024
#define NB ((NN + SCAN_BS - 1) / SCAN_BS)   // 98

// scratch (device globals)
__device__ unsigned g_xbq[NN * 32];    // packed int16 pair {q0,q1} per (node,o) — 12.8MB
__device__ float    g_s[NN];           // per-node decode scale
__device__ float    g_agg[NN * 32];    // agg init (loop term + bias)
__device__ float    g_h1[NN * 32];
__device__ float    g_h2[NN * 32];
__device__ float    g_h3[NN * 32];
__device__ int      g_deg[NN];
__device__ int      g_bsum[NB + 1];
__device__ int      g_rowptr[NN + 1];
__device__ int      g_cursor[NN];
__device__ int2     g_meta[NE];        // {src | etype<<17, mask_bits} grouped by dst
__device__ uint2    g_wq1[(INF / 2) * 96];  // pre-split bf16 {hipair, lopair} weights
__device__ uint2    g_wq2[(HID / 2) * 96];
__device__ uint2    g_wq3[(HID / 2) * 96];

// ---------------------------------------------------------------------------
// 64-row M-tile, 8 warps: warpM in {0,1} (32 rows), warpN in {0..3} (24 cols)
// K handled as bf16 m16n8k16; per 32-K chunk: 2 steps of 8 kpairs.
// ---------------------------------------------------------------------------
#define MROWS 64
#define XS_S 18      // uint2 stride per row (16 kpairs + pad, 16B-aligned rows)
#define WS_S 98      // uint2 stride per kpair row (96 cols + pad)
#define OS_STRIDE 104
#define XS_BYTES  (MROWS * XS_S * 8)              // 9216
#define WS_BYTES  (16 * WS_S * 8)                 // 12544
#define OUTS_BYTES (MROWS * OS_STRIDE * 4)        // 26624
#define TSMEM     (OUTS_BYTES + 256)              // outs dominates (staging 21760)

__device__ __forceinline__ void mma16(float* c, const unsigned* a, const unsigned* b) {
    asm volatile("mma.sync.aligned.m16n8k16.row.col.f32.bf16.bf16.f32 "
                 "{%0,%1,%2,%3}, {%4,%5,%6,%7}, {%8,%9}, {%0,%1,%2,%3};"
                 : "+f"(c[0]), "+f"(c[1]), "+f"(c[2]), "+f"(c[3])
                 : "r"(a[0]), "r"(a[1]), "r"(a[2]), "r"(a[3]), "r"(b[0]), "r"(b[1]));
}
// pack bf16(vlow), bf16(vhigh) into one reg: low half = vlow
__device__ __forceinline__ unsigned bfpack(float vhigh, float vlow) {
    unsigned r;
    asm("cvt.rn.bf16x2.f32 %0, %1, %2;" : "=r"(r) : "f"(vhigh), "f"(vlow));
    return r;
}
// split pair (v0=low elem, v1=high elem) into {hipair, lopair}
__device__ __forceinline__ uint2 bfsplit2(float v0, float v1) {
    unsigned hp = bfpack(v1, v0);
    float h0 = __uint_as_float(hp << 16);
    float h1 = __uint_as_float(hp & 0xFFFF0000u);
    unsigned lp = bfpack(v1 - h1, v0 - h0);
    return make_uint2(hp, lp);
}

// Pre-split weights into bf16 hi/lo kpairs: wq[kp*96+j] = split(W[2kp][j], W[2kp+1][j])
__global__ void k_wsplit(const float* __restrict__ V, const float* __restrict__ loopw,
                         uint2* __restrict__ wq, int DIN)
{
    int idx = blockIdx.x * blockDim.x + threadIdx.x;
    if (idx >= (DIN / 2) * 96) return;
    int kp = idx / 96, j = idx - kp * 96;
    int d0 = 2 * kp, d1 = 2 * kp + 1;
    float w0, w1;
    if (j < 64) {
        int b = j >> 5, o = j & 31;
        w0 = V[b * DIN * 32 + d0 * 32 + o];
        w1 = V[b * DIN * 32 + d1 * 32 + o];
    } else {
        w0 = loopw[d0 * 32 + (j - 64)];
        w1 = loopw[d1 * 32 + (j - 64)];
    }
    wq[idx] = bfsplit2(w0, w1);
}

// ---------------------------------------------------------------------------
// Split-BF16 tensor-core transform. 64 nodes/block.
// out96[n][j] = sum_d x[n][d]*Wall[d][j]  (j<64: basis; j>=64: loop)
// Epilogue: per-node scale s[n]; xbq packed int16 pair; agg init = loop + bias
// ---------------------------------------------------------------------------
template <int DIN>
__global__ __launch_bounds__(256, 3)
void transform_mma(const float* __restrict__ xin,
                   const uint2* __restrict__ wq,     // [DIN/2][96] pre-split
                   const float* __restrict__ bias,
                   unsigned* __restrict__ xbq,
                   float* __restrict__ sarr,
                   float* __restrict__ agg,
                   int nnodes)
{
    extern __shared__ char smraw[];
    uint2* xs = (uint2*)smraw;                   // [64][XS_S] {hipair, lopair}
    uint2* ws = (uint2*)(smraw + XS_BYTES);      // [16][WS_S]
    float* outs = (float*)smraw;                 // reused after compute

    const int tid = threadIdx.x;
    const int lane = tid & 31, wid = tid >> 5;
    const int warpM = wid & 1, warpN = wid >> 1;
    const int gid = lane >> 2, tig = lane & 3;
    const int base = blockIdx.x * MROWS;

    float c[2][3][4];
#pragma unroll
    for (int mt = 0; mt < 2; mt++)
#pragma unroll
        for (int nt = 0; nt < 3; nt++)
#pragma unroll
            for (int q = 0; q < 4; q++) c[mt][nt][q] = 0.f;

    const int NCHUNK = DIN / 32;
#pragma unroll 1
    for (int ch = 0; ch < NCHUNK; ch++) {
        const int kbase = ch * 32;
        if (ch) __syncthreads();
        // stage x chunk: 64 rows x 32 cols (=16 kpairs) via float4 + bf16 split
        for (int idx = tid; idx < MROWS * 8; idx += 256) {
            int row = idx >> 3, c4 = (idx & 7) * 4;      // 4 elems = 2 kpairs
            int node = base + row;
            float4 v = (node < nnodes)
                ? *(const float4*)(xin + (long)node * DIN + kbase + c4)
                : make_float4(0.f, 0.f, 0.f, 0.f);
            uint2 p0 = bfsplit2(v.x, v.y);
            uint2 p1 = bfsplit2(v.z, v.w);
            uint2* dst = &xs[row * XS_S + (c4 >> 1)];
            dst[0] = p0;
            dst[1] = p1;
        }
        // stage W chunk (pre-split): 16 kpairs x 96 via uint4 copies
        for (int idx = tid; idx < 16 * 48; idx += 256) {
            int kp = idx / 48, j2 = (idx % 48) * 2;
            uint4 v = *(const uint4*)&wq[((kbase >> 1) + kp) * 96 + j2];
            *(uint4*)&ws[kp * WS_S + j2] = v;
        }
        __syncthreads();

#pragma unroll
        for (int ks2 = 0; ks2 < 16; ks2 += 8) {    // two K=16 steps per chunk
            unsigned ahi[2][4], alo[2][4];
#pragma unroll
            for (int mt = 0; mt < 2; mt++) {
                int r0 = warpM * 32 + mt * 16 + gid;
                uint2 xa0 = xs[(r0    ) * XS_S + ks2 + tig];
                uint2 xa1 = xs[(r0 + 8) * XS_S + ks2 + tig];
                uint2 xa2 = xs[(r0    ) * XS_S + ks2 + tig + 4];
                uint2 xa3 = xs[(r0 + 8) * XS_S + ks2 + tig + 4];
                ahi[mt][0] = xa0.x; alo[mt][0] = xa0.y;
                ahi[mt][1] = xa1.x; alo[mt][1] = xa1.y;
                ahi[mt][2] = xa2.x; alo[mt][2] = xa2.y;
                ahi[mt][3] = xa3.x; alo[mt][3] = xa3.y;
            }
            unsigned bhi[3][2], blo[3][2];
#pragma unroll
            for (int nt = 0; nt < 3; nt++) {
                int n = warpN * 24 + nt * 8 + gid;
                uint2 wb0 = ws[(ks2 + tig    ) * WS_S + n];
                uint2 wb1 = ws[(ks2 + tig + 4) * WS_S + n];
                bhi[nt][0] = wb0.x; blo[nt][0] = wb0.y;
                bhi[nt][1] = wb1.x; blo[nt][1] = wb1.y;
            }
#pragma unroll
            for (int mt = 0; mt < 2; mt++)
#pragma unroll
                for (int nt = 0; nt < 3; nt++) {
                    mma16(c[mt][nt], ahi[mt], bhi[nt]);
                    mma16(c[mt][nt], ahi[mt], blo[nt]);
                    mma16(c[mt][nt], alo[mt], bhi[nt]);
                }
        }
    }
    __syncthreads();   // compute smem dead; reuse as outs

#pragma unroll
    for (int mt = 0; mt < 2; mt++)
#pragma unroll
        for (int nt = 0; nt < 3; nt++) {
            int r0 = warpM * 32 + mt * 16 + gid;
            int c0 = warpN * 24 + nt * 8 + tig * 2;
            outs[(r0    ) * OS_STRIDE + c0    ] = c[mt][nt][0];
            outs[(r0    ) * OS_STRIDE + c0 + 1] = c[mt][nt][1];
            outs[(r0 + 8) * OS_STRIDE + c0    ] = c[mt][nt][2];
            outs[(r0 + 8) * OS_STRIDE + c0 + 1] = c[mt][nt][3];
        }
    __syncthreads();

    // Epilogue: per-node max -> scale; quantize basis pair; agg init.
    for (int idx = tid; idx < MROWS * 32; idx += 256) {
        int row = idx >> 5, o = idx & 31;
        int node = base + row;
        float v0 = outs[row * OS_STRIDE + o];
        float v1 = outs[row * OS_STRIDE + 32 + o];
        float m = fmaxf(fabsf(v0), fabsf(v1));
#pragma unroll
        for (int off = 16; off; off >>= 1)
            m = fmaxf(m, __shfl_xor_sync(0xFFFFFFFFu, m, off));
        float k = (m > 1e-20f) ? 32767.0f / m : 0.f;
        int q0 = __float2int_rn(v0 * k);
        int q1 = __float2int_rn(v1 * k);
        unsigned pk = ((unsigned)q0 & 0xFFFFu) | ((unsigned)q1 << 16);
        if (node < nnodes) {
            xbq[(long)node * 32 + o] = pk;
            if (o == 0) sarr[node] = (m > 1e-20f) ? m * (1.0f / 32767.0f) : 0.f;
            agg[(long)node * 32 + o] = outs[row * OS_STRIDE + 64 + o] + bias[o];
        }
    }
}

// ------------------------ CSR build ---------------------------------------
__global__ void k_zero(int* p, int n)
{
    int i = blockIdx.x * blockDim.x + threadIdx.x;
    if (i < n) p[i] = 0;
}
__global__ void k_hist(const int* __restrict__ dst, int* __restrict__ deg, int ne)
{
    int i = blockIdx.x * blockDim.x + threadIdx.x;
    if (i < ne) atomicAdd(&deg[dst[i]], 1);
}
__global__ void k_blocksum(const int* __restrict__ deg, int* __restrict__ bsum, int n)
{
    __shared__ int wsum[32];
    int i = blockIdx.x * SCAN_BS + threadIdx.x;
    int v = (i < n) ? deg[i] : 0;
#pragma unroll
    for (int o = 16; o; o >>= 1) v += __shfl_down_sync(0xFFFFFFFFu, v, o);
    int lane = threadIdx.x & 31, wid = threadIdx.x >> 5;
    if (lane == 0) wsum[wid] = v;
    __syncthreads();
    if (wid == 0) {
        int x = wsum[lane];
#pragma unroll
        for (int o = 16; o; o >>= 1) x += __shfl_down_sync(0xFFFFFFFFu, x, o);
        if (lane == 0) bsum[blockIdx.x] = x;
    }
}
__global__ void k_scantop(int* __restrict__ bsum, int nb, int* __restrict__ rowptr_end)
{
    __shared__ int s[128];
    int t = threadIdx.x;
    int v = (t < nb) ? bsum[t] : 0;
    s[t] = v;
    __syncthreads();
#pragma unroll
    for (int o = 1; o < 128; o <<= 1) {
        int y = (t >= o) ? s[t - o] : 0;
        __syncthreads();
        s[t] += y;
        __syncthreads();
    }
    if (t < nb) bsum[t] = s[t] - v;
    if (t == 127) *rowptr_end = s[127];
}
__global__ void k_scanapply(const int* __restrict__ deg, const int* __restrict__ bsum,
                            int* __restrict__ rowptr, int* __restrict__ cursor, int n)
{
    __shared__ int wsum[32];
    int i = blockIdx.x * SCAN_BS + threadIdx.x;
    int v = (i < n) ? deg[i] : 0;
    int lane = threadIdx.x & 31, wid = threadIdx.x >> 5;
    unsigned fm = 0xFFFFFFFFu;
    int x = v;
#pragma unroll
    for (int o = 1; o < 32; o <<= 1) {
        int y = __shfl_up_sync(fm, x, o);
        if (lane >= o) x += y;
    }
    if (lane == 31) wsum[wid] = x;
    __syncthreads();
    if (wid == 0) {
        int w = wsum[lane];
        int wx = w;
#pragma unroll
        for (int o = 1; o < 32; o <<= 1) {
            int y = __shfl_up_sync(fm, wx, o);
            if (lane >= o) wx += y;
        }
        wsum[lane] = wx - w;
    }
    __syncthreads();
    int excl = (x - v) + wsum[wid] + bsum[blockIdx.x];
    if (i < n) { rowptr[i] = excl; cursor[i] = excl; }
}
__global__ void k_scatter(const int* __restrict__ src, const int* __restrict__ dst,
                          const int* __restrict__ etype, const float* __restrict__ mask,
                          int* __restrict__ cursor, int2* __restrict__ meta, int ne)
{
    int e = blockIdx.x * blockDim.x + threadIdx.x;
    if (e >= ne) return;
    int d = dst[e];
    int pos = atomicAdd(&cursor[d], 1);
    meta[pos] = make_int2(src[e] | (etype[e] << 17), __float_as_int(mask[e]));
}

// ---------------------------------------------------------------------------
// Aggregate: warp per node, 8-deep load batching for MLP.
// ---------------------------------------------------------------------------
__global__ void k_aggregate(const unsigned* __restrict__ xbq,
                            const float* __restrict__ sarr,
                            const float* __restrict__ agginit,
                            const int* __restrict__ rowptr,
                            const int2* __restrict__ meta,
                            const float* __restrict__ comp,
                            float* __restrict__ h, int nn)
{
    __shared__ float cl[16];
    if (threadIdx.x < 10) cl[threadIdx.x] = comp[threadIdx.x];
    __syncthreads();
    const int lane = threadIdx.x & 31;
    const int w = (blockIdx.x * blockDim.x + threadIdx.x) >> 5;
    if (w >= nn) return;
    float acc = agginit[(long)w * 32 + lane];
    int i = rowptr[w];
    const int end = rowptr[w + 1];
    for (; i + 8 <= end; i += 8) {
        int2 mm[8];
#pragma unroll
        for (int j = 0; j < 8; j++) mm[j] = __ldg(&meta[i + j]);
        unsigned uu[8];
#pragma unroll
        for (int j = 0; j < 8; j++)
            uu[j] = __ldg(&xbq[(long)(mm[j].x & 0x1FFFF) * 32 + lane]);
        float tv[8];
#pragma unroll
        for (int j = 0; j < 8; j++)
            tv[j] = __int_as_float(mm[j].y) * __ldg(&sarr[mm[j].x & 0x1FFFF]);
#pragma unroll
        for (int j = 0; j < 8; j++) {
            int r = (mm[j].x >> 17) * 2;
            float a = (float)((int)(uu[j] << 16) >> 16);
            float b = (float)((int)uu[j] >> 16);
            acc = fmaf(tv[j], fmaf(cl[r], a, cl[r + 1] * b), acc);
        }
    }
    for (; i + 4 <= end; i += 4) {
        int2 mm[4];
#pragma unroll
        for (int j = 0; j < 4; j++) mm[j] = __ldg(&meta[i + j]);
        unsigned uu[4];
#pragma unroll
        for (int j = 0; j < 4; j++)
            uu[j] = __ldg(&xbq[(long)(mm[j].x & 0x1FFFF) * 32 + lane]);
#pragma unroll
        for (int j = 0; j < 4; j++) {
            float tvj = __int_as_float(mm[j].y) * __ldg(&sarr[mm[j].x & 0x1FFFF]);
            int r = (mm[j].x >> 17) * 2;
            float a = (float)((int)(uu[j] << 16) >> 16);
            float b = (float)((int)uu[j] >> 16);
            acc = fmaf(tvj, fmaf(cl[r], a, cl[r + 1] * b), acc);
        }
    }
    for (; i < end; i++) {
        int2 md = __ldg(&meta[i]);
        int sidx = md.x & 0x1FFFF;
        float tv = __int_as_float(md.y) * __ldg(&sarr[sidx]);
        unsigned u = __ldg(&xbq[(long)sidx * 32 + lane]);
        int r = (md.x >> 17) * 2;
        float a = (float)((int)(u << 16) >> 16), b = (float)((int)u >> 16);
        acc = fmaf(tv, fmaf(cl[r], a, cl[r + 1] * b), acc);
    }
    h[(long)w * 32 + lane] = tanhf(acc);
}

// ---------------------------------------------------------------------------
#define PPB 32
__global__ void head_kernel(const float* __restrict__ h1,
                            const float* __restrict__ h2,
                            const float* __restrict__ h3,
                            const int* __restrict__ users,
                            const int* __restrict__ items,
                            const float* __restrict__ w1,
                            const float* __restrict__ bw1,
                            const float* __restrict__ w2,
                            const float* __restrict__ bw2,
                            float* __restrict__ out,
                            int npairs)
{
    extern __shared__ float sm[];
    float* w1s = sm;
    float* feats = sm + 24576;
    const int tid = threadIdx.x;

    for (int idx = tid; idx < 24576; idx += 128) w1s[idx] = w1[idx];
    const float bb = bw1[tid];
    const float wv2 = w2[tid];
    const float b2v = bw2[0];
    __shared__ float red[4];
    __syncthreads();

    const int pend = min((blockIdx.x + 1) * PPB, npairs);
    for (int p = blockIdx.x * PPB; p < pend; p++) {
        if (tid < 96) {
            int u = __ldg(&users[p]);
            int it = __ldg(&items[p]);
            int o = tid & 31;
            const float* hu = (tid < 32) ? h1 : (tid < 64) ? h2 : h3;
            feats[tid] = hu[(long)u * 32 + o];
            feats[96 + tid] = hu[(long)it * 32 + o];
        }
        __syncthreads();
        float acc = bb;
#pragma unroll 16
        for (int k = 0; k < 192; k++)
            acc = fmaf(feats[k], w1s[k * 128 + tid], acc);
        float hv = fmaxf(acc, 0.f) * wv2;
#pragma unroll
        for (int off = 16; off; off >>= 1) hv += __shfl_down_sync(0xFFFFFFFFu, hv, off);
        if ((tid & 31) == 0) red[tid >> 5] = hv;
        __syncthreads();
        if (tid == 0) out[p] = red[0] + red[1] + red[2] + red[3] + b2v;
        __syncthreads();
    }
}

// ---------------------------------------------------------------------------
extern "C" void kernel_launch(void* const* d_in, const int* in_sizes, int n_in,
                              void* d_out, int out_size)
{
    const float* x     = (const float*)d_in[0];
    const float* emask = (const float*)d_in[1];
    const int*   etype = (const int*)d_in[2];
    const int*   src   = (const int*)d_in[3];
    const int*   dst   = (const int*)d_in[4];
    const int*   users = (const int*)d_in[5];
    const int*   items = (const int*)d_in[6];
    const float* V1    = (const float*)d_in[7];
    const float* comp1 = (const float*)d_in[8];
    const float* loop1 = (const float*)d_in[9];
    const float* b1    = (const float*)d_in[10];
    const float* V2    = (const float*)d_in[11];
    const float* comp2 = (const float*)d_in[12];
    const float* loop2 = (const float*)d_in[13];
    const float* b2    = (const float*)d_in[14];
    const float* V3    = (const float*)d_in[15];
    const float* comp3 = (const float*)d_in[16];
    const float* loop3 = (const float*)d_in[17];
    const float* b3    = (const float*)d_in[18];
    const float* w1    = (const float*)d_in[19];
    const float* bw1   = (const float*)d_in[20];
    const float* w2    = (const float*)d_in[21];
    const float* bw2   = (const float*)d_in[22];
    float* out = (float*)d_out;

    unsigned* xbq;
    float *sarr, *agg, *h1, *h2, *h3;
    uint2 *wq1, *wq2, *wq3;
    int *deg, *bsum, *rowptr, *cursor;
    int2* meta;
    cudaGetSymbolAddress((void**)&xbq,    g_xbq);
    cudaGetSymbolAddress((void**)&sarr,   g_s);
    cudaGetSymbolAddress((void**)&agg,    g_agg);
    cudaGetSymbolAddress((void**)&h1,     g_h1);
    cudaGetSymbolAddress((void**)&h2,     g_h2);
    cudaGetSymbolAddress((void**)&h3,     g_h3);
    cudaGetSymbolAddress((void**)&deg,    g_deg);
    cudaGetSymbolAddress((void**)&bsum,   g_bsum);
    cudaGetSymbolAddress((void**)&rowptr, g_rowptr);
    cudaGetSymbolAddress((void**)&cursor, g_cursor);
    cudaGetSymbolAddress((void**)&meta,   g_meta);
    cudaGetSymbolAddress((void**)&wq1,    g_wq1);
    cudaGetSymbolAddress((void**)&wq2,    g_wq2);
    cudaGetSymbolAddress((void**)&wq3,    g_wq3);

    const int smem_hd = (24576 + 192) * 4;
    cudaFuncSetAttribute(transform_mma<INF>, cudaFuncAttributeMaxDynamicSharedMemorySize, TSMEM);
    cudaFuncSetAttribute(transform_mma<HID>, cudaFuncAttributeMaxDynamicSharedMemorySize, TSMEM);
    cudaFuncSetAttribute(head_kernel, cudaFuncAttributeMaxDynamicSharedMemorySize, smem_hd);

    const int tgrid = (NN + MROWS - 1) / MROWS;   // 1563
    const int agrid = (NN * 32 + 255) / 256;      // 12500
    const int egrid = (NE + 255) / 256;

    static cudaStream_t s2 = nullptr;
    static cudaEvent_t ev0 = nullptr, ev1 = nullptr;
    if (!s2) {
        cudaStreamCreateWithFlags(&s2, cudaStreamNonBlocking);
        cudaEventCreateWithFlags(&ev0, cudaEventDisableTiming);
        cudaEventCreateWithFlags(&ev1, cudaEventDisableTiming);
    }

    // fork: CSR build + layer-2/3 weight prep on s2, overlapping transform1
    cudaEventRecord(ev0, 0);
    cudaStreamWaitEvent(s2, ev0, 0);

    // main stream: layer-1 weight prep + transform (index-2 launch)
    k_wsplit<<<((INF / 2) * 96 + 255) / 256, 256>>>(V1, loop1, wq1, INF);
    transform_mma<INF><<<tgrid, 256, TSMEM>>>(x, wq1, b1, xbq, sarr, agg, NN);

    // side stream
    k_wsplit<<<((HID / 2) * 96 + 255) / 256, 256, 0, s2>>>(V2, loop2, wq2, HID);
    k_wsplit<<<((HID / 2) * 96 + 255) / 256, 256, 0, s2>>>(V3, loop3, wq3, HID);
    k_zero<<<(NN + 255) / 256, 256, 0, s2>>>(deg, NN);
    k_hist<<<egrid, 256, 0, s2>>>(dst, deg, NE);
    k_blocksum<<<NB, SCAN_BS, 0, s2>>>(deg, bsum, NN);
    k_scantop<<<1, 128, 0, s2>>>(bsum, NB, rowptr + NN);
    k_scanapply<<<NB, SCAN_BS, 0, s2>>>(deg, bsum, rowptr, cursor, NN);
    k_scatter<<<egrid, 256, 0, s2>>>(src, dst, etype, emask, cursor, meta, NE);

    // join
    cudaEventRecord(ev1, s2);
    cudaStreamWaitEvent(0, ev1, 0);

    // Layer 1 aggregate
    k_aggregate<<<agrid, 256>>>(xbq, sarr, agg, rowptr, meta, comp1, h1, NN);
    // Layer 2
    transform_mma<HID><<<tgrid, 256, TSMEM>>>(h1, wq2, b2, xbq, sarr, agg, NN);
    k_aggregate<<<agrid, 256>>>(xbq, sarr, agg, rowptr, meta, comp2, h2, NN);
    // Layer 3
    transform_mma<HID><<<tgrid, 256, TSMEM>>>(h2, wq3, b3, xbq, sarr, agg, NN);
    k_aggregate<<<agrid, 256>>>(xbq, sarr, agg, rowptr, meta, comp3, h3, NN);
    // Head
    head_kernel<<<(NPAIRS + PPB - 1) / PPB, 128, smem_hd>>>(
        h1, h2, h3, users, items, w1, bw1, w2, bw2, out, NPAIRS);
}